// round 3
// baseline (speedup 1.0000x reference)
#include <cuda_runtime.h>
#include <cstdint>

#define D_IN   1024
#define D_OUT  1024
#define NH     16
#define HD     64
#define BB     4
#define TT     2048
#define NROWS  (BB*TT)   // 8192

// ---------------------------------------------------------------------------
// Scratch for Q,K,V in [B*H, T, HD] layout (32 MB each). Static __device__
// arrays per allocation-guard rules.
// ---------------------------------------------------------------------------
__device__ float g_Q[BB*NH*TT*HD];
__device__ float g_K[BB*NH*TT*HD];
__device__ float g_V[BB*NH*TT*HD];

// cvt.rna.tf32.f32 must write a .b32 register (ptxas rejects an .f32 dest).
__device__ __forceinline__ float to_tf32(float x) {
    uint32_t u;
    asm("cvt.rna.tf32.f32 %0, %1;" : "=r"(u) : "f"(x));
    return __uint_as_float(u);
}

__device__ __forceinline__ void mma_tf32(float& c0, float& c1, float& c2, float& c3,
                                         uint32_t a0, uint32_t a1, uint32_t a2, uint32_t a3,
                                         uint32_t b0, uint32_t b1) {
    asm volatile(
        "mma.sync.aligned.m16n8k8.row.col.f32.tf32.tf32.f32 "
        "{%0,%1,%2,%3}, {%4,%5,%6,%7}, {%8,%9}, {%0,%1,%2,%3};\n"
        : "+f"(c0), "+f"(c1), "+f"(c2), "+f"(c3)
        : "r"(a0), "r"(a1), "r"(a2), "r"(a3), "r"(b0), "r"(b1));
}

// ---------------------------------------------------------------------------
// Kernel A: QKV projection.
// grid = (8192/128, 1024/128, 3), block = 256 (8 warps, 4x2 warp grid,
// warp tile 32x64). K-tile = 32. Output scattered into [B,H,T,HD].
// ---------------------------------------------------------------------------
__global__ __launch_bounds__(256) void qkv_kernel(
    const float* __restrict__ X,
    const float* __restrict__ Wq, const float* __restrict__ bq,
    const float* __restrict__ Wk, const float* __restrict__ bk,
    const float* __restrict__ Wv, const float* __restrict__ bv)
{
    __shared__ float As[128 * 36];   // padded stride 36 -> conflict-free A frags
    __shared__ float Bs[32 * 136];   // padded stride 136 -> conflict-free B frags

    const float* W;
    const float* bias;
    float* dst;
    if (blockIdx.z == 0)      { W = Wq; bias = bq; dst = g_Q; }
    else if (blockIdx.z == 1) { W = Wk; bias = bk; dst = g_K; }
    else                      { W = Wv; bias = bv; dst = g_V; }

    const int m0blk = blockIdx.x * 128;
    const int n0blk = blockIdx.y * 128;
    const int tid  = threadIdx.x;
    const int lane = tid & 31;
    const int warp = tid >> 5;
    const int wm = (warp >> 1) * 32;   // warp M offset inside block
    const int wn = (warp & 1) * 64;    // warp N offset inside block

    float c[2][8][4];
#pragma unroll
    for (int mi = 0; mi < 2; mi++)
#pragma unroll
        for (int nb = 0; nb < 8; nb++)
#pragma unroll
            for (int j = 0; j < 4; j++) c[mi][nb][j] = 0.f;

    for (int k0 = 0; k0 < D_IN; k0 += 32) {
        __syncthreads();
        // load A tile 128x32 (4 float4 per thread)
#pragma unroll
        for (int i = 0; i < 4; i++) {
            int f4  = tid + i * 256;
            int row = f4 >> 3;
            int c4  = (f4 & 7) * 4;
            float4 v = *(const float4*)(X + (size_t)(m0blk + row) * D_IN + k0 + c4);
            v.x = to_tf32(v.x); v.y = to_tf32(v.y); v.z = to_tf32(v.z); v.w = to_tf32(v.w);
            *(float4*)(As + row * 36 + c4) = v;
        }
        // load B tile 32x128
#pragma unroll
        for (int i = 0; i < 4; i++) {
            int f4  = tid + i * 256;
            int row = f4 >> 5;
            int c4  = (f4 & 31) * 4;
            float4 v = *(const float4*)(W + (size_t)(k0 + row) * D_OUT + n0blk + c4);
            v.x = to_tf32(v.x); v.y = to_tf32(v.y); v.z = to_tf32(v.z); v.w = to_tf32(v.w);
            *(float4*)(Bs + row * 136 + c4) = v;
        }
        __syncthreads();

#pragma unroll
        for (int ks = 0; ks < 4; ks++) {
            uint32_t a[2][4];
#pragma unroll
            for (int mi = 0; mi < 2; mi++) {
                int r  = wm + mi * 16 + (lane >> 2);
                int cc = ks * 8 + (lane & 3);
                a[mi][0] = __float_as_uint(As[r * 36 + cc]);
                a[mi][1] = __float_as_uint(As[(r + 8) * 36 + cc]);
                a[mi][2] = __float_as_uint(As[r * 36 + cc + 4]);
                a[mi][3] = __float_as_uint(As[(r + 8) * 36 + cc + 4]);
            }
#pragma unroll
            for (int nb = 0; nb < 8; nb++) {
                int col = wn + nb * 8 + (lane >> 2);
                int kr  = ks * 8 + (lane & 3);
                uint32_t b0 = __float_as_uint(Bs[kr * 136 + col]);
                uint32_t b1 = __float_as_uint(Bs[(kr + 4) * 136 + col]);
                mma_tf32(c[0][nb][0], c[0][nb][1], c[0][nb][2], c[0][nb][3],
                         a[0][0], a[0][1], a[0][2], a[0][3], b0, b1);
                mma_tf32(c[1][nb][0], c[1][nb][1], c[1][nb][2], c[1][nb][3],
                         a[1][0], a[1][1], a[1][2], a[1][3], b0, b1);
            }
        }
    }

    // epilogue: bias + scatter to [B,H,T,HD]
#pragma unroll
    for (int mi = 0; mi < 2; mi++) {
#pragma unroll
        for (int nb = 0; nb < 8; nb++) {
            int row = m0blk + wm + mi * 16 + (lane >> 2);
            int col = n0blk + wn + nb * 8 + 2 * (lane & 3);
            int b_ = row >> 11;        // /2048
            int t_ = row & 2047;
            int h  = col >> 6;
            int d  = col & 63;
            float bv0 = bias[col];
            float bv1 = bias[col + 1];
            size_t base = (((size_t)(b_ * NH + h)) * TT) * HD;
            float2 v0 = make_float2(c[mi][nb][0] + bv0, c[mi][nb][1] + bv1);
            float2 v1 = make_float2(c[mi][nb][2] + bv0, c[mi][nb][3] + bv1);
            *(float2*)(dst + base + (size_t)t_ * HD + d)       = v0;
            *(float2*)(dst + base + (size_t)(t_ + 8) * HD + d) = v1;
        }
    }
}

// ---------------------------------------------------------------------------
// Kernel B: causal flash attention over one (b,h), 64 query rows per CTA.
// block = 128 threads (4 warps x 16 q-rows). KV tiles of 64.
// grid = (T/64, B*NH).
// ---------------------------------------------------------------------------
__global__ __launch_bounds__(128) void attn_kernel(float* __restrict__ out)
{
    __shared__ float sK[64 * 68];   // K tile; reused for Q staging and P
    __shared__ float sV[64 * 68];   // V tile

    const int bh  = blockIdx.y;       // b*16 + h
    const int qt  = blockIdx.x;       // query tile
    const int tid = threadIdx.x;
    const int lane = tid & 31;
    const int warp = tid >> 5;

    const float* Qb = g_Q + (size_t)bh * TT * HD;
    const float* Kb = g_K + (size_t)bh * TT * HD;
    const float* Vb = g_V + (size_t)bh * TT * HD;

    const int q0 = qt * 64;

    // stage Q tile into sK, then pull warp's A-fragments into registers
#pragma unroll
    for (int i = 0; i < 8; i++) {
        int f4  = tid + i * 128;
        int row = f4 >> 4;
        int c4  = (f4 & 15) * 4;
        float4 v = *(const float4*)(Qb + (size_t)(q0 + row) * HD + c4);
        v.x = to_tf32(v.x); v.y = to_tf32(v.y); v.z = to_tf32(v.z); v.w = to_tf32(v.w);
        *(float4*)(sK + row * 68 + c4) = v;
    }
    __syncthreads();

    uint32_t qa[8][4];
    {
        int r = warp * 16 + (lane >> 2);
#pragma unroll
        for (int ks = 0; ks < 8; ks++) {
            int cc = ks * 8 + (lane & 3);
            qa[ks][0] = __float_as_uint(sK[r * 68 + cc]);
            qa[ks][1] = __float_as_uint(sK[(r + 8) * 68 + cc]);
            qa[ks][2] = __float_as_uint(sK[r * 68 + cc + 4]);
            qa[ks][3] = __float_as_uint(sK[(r + 8) * 68 + cc + 4]);
        }
    }

    float o[8][4];
#pragma unroll
    for (int nb = 0; nb < 8; nb++)
#pragma unroll
        for (int j = 0; j < 4; j++) o[nb][j] = 0.f;
    float m0 = -1e30f, m1 = -1e30f, l0 = 0.f, l1 = 0.f;

    const int qrow0 = q0 + warp * 16 + (lane >> 2);
    const int qrow1 = qrow0 + 8;

    for (int kt = 0; kt <= qt; kt++) {
        __syncthreads();   // previous tile's P/V smem reads (and Q staging) done
        // load K,V tiles (64x64 each)
#pragma unroll
        for (int i = 0; i < 8; i++) {
            int f4  = tid + i * 128;
            int row = f4 >> 4;
            int c4  = (f4 & 15) * 4;
            size_t g = (size_t)(kt * 64 + row) * HD + c4;
            float4 kv = *(const float4*)(Kb + g);
            kv.x = to_tf32(kv.x); kv.y = to_tf32(kv.y); kv.z = to_tf32(kv.z); kv.w = to_tf32(kv.w);
            *(float4*)(sK + row * 68 + c4) = kv;
            float4 vv = *(const float4*)(Vb + g);
            vv.x = to_tf32(vv.x); vv.y = to_tf32(vv.y); vv.z = to_tf32(vv.z); vv.w = to_tf32(vv.w);
            *(float4*)(sV + row * 68 + c4) = vv;
        }
        __syncthreads();

        // S = Q * K^T  (warp's 16 rows x 64 kv)
        float s[8][4];
#pragma unroll
        for (int nb = 0; nb < 8; nb++)
#pragma unroll
            for (int j = 0; j < 4; j++) s[nb][j] = 0.f;

#pragma unroll
        for (int ks = 0; ks < 8; ks++) {
#pragma unroll
            for (int nb = 0; nb < 8; nb++) {
                int n  = nb * 8 + (lane >> 2);
                int kk = ks * 8 + (lane & 3);
                uint32_t b0 = __float_as_uint(sK[n * 68 + kk]);
                uint32_t b1 = __float_as_uint(sK[n * 68 + kk + 4]);
                mma_tf32(s[nb][0], s[nb][1], s[nb][2], s[nb][3],
                         qa[ks][0], qa[ks][1], qa[ks][2], qa[ks][3], b0, b1);
            }
        }

        // scale, causal mask, online softmax
        const bool diag = (kt == qt);
        float tm0 = -1e30f, tm1 = -1e30f;
#pragma unroll
        for (int nb = 0; nb < 8; nb++) {
            int kv = kt * 64 + nb * 8 + 2 * (lane & 3);
            s[nb][0] *= 0.125f; if (diag && kv     > qrow0) s[nb][0] = -1e30f;
            s[nb][1] *= 0.125f; if (diag && kv + 1 > qrow0) s[nb][1] = -1e30f;
            s[nb][2] *= 0.125f; if (diag && kv     > qrow1) s[nb][2] = -1e30f;
            s[nb][3] *= 0.125f; if (diag && kv + 1 > qrow1) s[nb][3] = -1e30f;
            tm0 = fmaxf(tm0, fmaxf(s[nb][0], s[nb][1]));
            tm1 = fmaxf(tm1, fmaxf(s[nb][2], s[nb][3]));
        }
        tm0 = fmaxf(tm0, __shfl_xor_sync(0xffffffffu, tm0, 1));
        tm0 = fmaxf(tm0, __shfl_xor_sync(0xffffffffu, tm0, 2));
        tm1 = fmaxf(tm1, __shfl_xor_sync(0xffffffffu, tm1, 1));
        tm1 = fmaxf(tm1, __shfl_xor_sync(0xffffffffu, tm1, 2));

        float mn0 = fmaxf(m0, tm0), mn1 = fmaxf(m1, tm1);
        float al0 = __expf(m0 - mn0), al1 = __expf(m1 - mn1);
        float rs0 = 0.f, rs1 = 0.f;
#pragma unroll
        for (int nb = 0; nb < 8; nb++) {
            s[nb][0] = __expf(s[nb][0] - mn0); rs0 += s[nb][0];
            s[nb][1] = __expf(s[nb][1] - mn0); rs0 += s[nb][1];
            s[nb][2] = __expf(s[nb][2] - mn1); rs1 += s[nb][2];
            s[nb][3] = __expf(s[nb][3] - mn1); rs1 += s[nb][3];
            o[nb][0] *= al0; o[nb][1] *= al0;
            o[nb][2] *= al1; o[nb][3] *= al1;
        }
        rs0 += __shfl_xor_sync(0xffffffffu, rs0, 1);
        rs0 += __shfl_xor_sync(0xffffffffu, rs0, 2);
        rs1 += __shfl_xor_sync(0xffffffffu, rs1, 1);
        rs1 += __shfl_xor_sync(0xffffffffu, rs1, 2);
        l0 = l0 * al0 + rs0;
        l1 = l1 * al1 + rs1;
        m0 = mn0; m1 = mn1;

        __syncthreads();   // all warps finished reading K before P overwrites it
        // store P into sK (warp-private 16-row slice)
        {
            int r = warp * 16 + (lane >> 2);
#pragma unroll
            for (int nb = 0; nb < 8; nb++) {
                int cc = nb * 8 + 2 * (lane & 3);
                sK[r * 68 + cc]           = to_tf32(s[nb][0]);
                sK[r * 68 + cc + 1]       = to_tf32(s[nb][1]);
                sK[(r + 8) * 68 + cc]     = to_tf32(s[nb][2]);
                sK[(r + 8) * 68 + cc + 1] = to_tf32(s[nb][3]);
            }
        }
        __syncwarp();

        // O += P * V
        {
            int r = warp * 16 + (lane >> 2);
#pragma unroll
            for (int kc = 0; kc < 8; kc++) {
                int cc = kc * 8 + (lane & 3);
                uint32_t pa0 = __float_as_uint(sK[r * 68 + cc]);
                uint32_t pa1 = __float_as_uint(sK[(r + 8) * 68 + cc]);
                uint32_t pa2 = __float_as_uint(sK[r * 68 + cc + 4]);
                uint32_t pa3 = __float_as_uint(sK[(r + 8) * 68 + cc + 4]);
#pragma unroll
                for (int nb = 0; nb < 8; nb++) {
                    int d  = nb * 8 + (lane >> 2);
                    int kk = kc * 8 + (lane & 3);
                    uint32_t vb0 = __float_as_uint(sV[kk * 68 + d]);
                    uint32_t vb1 = __float_as_uint(sV[(kk + 4) * 68 + d]);
                    mma_tf32(o[nb][0], o[nb][1], o[nb][2], o[nb][3],
                             pa0, pa1, pa2, pa3, vb0, vb1);
                }
            }
        }
    }

    // normalize and write out[b, t, h*64 + d]
    float inv0 = 1.f / l0;
    float inv1 = 1.f / l1;
    int b_ = bh >> 4;
    int h  = bh & 15;
    float* orow0 = out + ((size_t)b_ * TT + qrow0) * D_OUT + h * HD;
    float* orow1 = out + ((size_t)b_ * TT + qrow1) * D_OUT + h * HD;
#pragma unroll
    for (int nb = 0; nb < 8; nb++) {
        int cc = nb * 8 + 2 * (lane & 3);
        *(float2*)(orow0 + cc) = make_float2(o[nb][0] * inv0, o[nb][1] * inv0);
        *(float2*)(orow1 + cc) = make_float2(o[nb][2] * inv1, o[nb][3] * inv1);
    }
}

// ---------------------------------------------------------------------------
extern "C" void kernel_launch(void* const* d_in, const int* in_sizes, int n_in,
                              void* d_out, int out_size)
{
    const float* X  = (const float*)d_in[0];
    const float* Wq = (const float*)d_in[1];
    const float* bq = (const float*)d_in[2];
    const float* Wk = (const float*)d_in[3];
    const float* bk = (const float*)d_in[4];
    const float* Wv = (const float*)d_in[5];
    const float* bv = (const float*)d_in[6];
    float* out = (float*)d_out;

    dim3 gA(NROWS / 128, D_OUT / 128, 3);
    qkv_kernel<<<gA, 256>>>(X, Wq, bq, Wk, bk, Wv, bv);

    dim3 gB(TT / 64, BB * NH);
    attn_kernel<<<gB, 128>>>(out);
}

// round 6
// speedup vs baseline: 1.0906x; 1.0906x over previous
#include <cuda_runtime.h>
#include <cstdint>

#define D_IN   1024
#define D_OUT  1024
#define NH     16
#define HD     64
#define BB     4
#define TT     2048
#define NROWS  (BB*TT)   // 8192

// ---------------------------------------------------------------------------
// Scratch (static __device__ per allocation-guard rules)
// ---------------------------------------------------------------------------
__device__ float g_Q[BB*NH*TT*HD];
__device__ float g_K[BB*NH*TT*HD];
__device__ float g_V[BB*NH*TT*HD];
__device__ float g_X[NROWS*D_IN];          // tf32-rounded copy of inputs
__device__ float g_W[3][D_IN*D_OUT];       // tf32-rounded copies of Wq,Wk,Wv

__device__ __forceinline__ float to_tf32(float x) {
    uint32_t u;
    asm("cvt.rna.tf32.f32 %0, %1;" : "=r"(u) : "f"(x));
    return __uint_as_float(u);
}

__device__ __forceinline__ void mma_tf32(float& c0, float& c1, float& c2, float& c3,
                                         uint32_t a0, uint32_t a1, uint32_t a2, uint32_t a3,
                                         uint32_t b0, uint32_t b1) {
    asm volatile(
        "mma.sync.aligned.m16n8k8.row.col.f32.tf32.tf32.f32 "
        "{%0,%1,%2,%3}, {%4,%5,%6,%7}, {%8,%9}, {%0,%1,%2,%3};\n"
        : "+f"(c0), "+f"(c1), "+f"(c2), "+f"(c3)
        : "r"(a0), "r"(a1), "r"(a2), "r"(a3), "r"(b0), "r"(b1));
}

__device__ __forceinline__ uint32_t smem_u32(const void* p) {
    return (uint32_t)__cvta_generic_to_shared(p);
}
__device__ __forceinline__ void cp_async16(uint32_t dst, const void* src) {
    asm volatile("cp.async.cg.shared.global [%0], [%1], 16;" :: "r"(dst), "l"(src));
}
__device__ __forceinline__ void cp_commit() {
    asm volatile("cp.async.commit_group;");
}
template <int N>
__device__ __forceinline__ void cp_wait() {
    asm volatile("cp.async.wait_group %0;" :: "n"(N));
}

// ---------------------------------------------------------------------------
// Kernel 0: tf32-round inputs into scratch (grid-stride, float4)
// ---------------------------------------------------------------------------
__global__ void prep_kernel(const float* __restrict__ src, float* __restrict__ dst, int n4)
{
    int i = blockIdx.x * blockDim.x + threadIdx.x;
    int stride = gridDim.x * blockDim.x;
    for (; i < n4; i += stride) {
        float4 v = ((const float4*)src)[i];
        v.x = to_tf32(v.x); v.y = to_tf32(v.y); v.z = to_tf32(v.z); v.w = to_tf32(v.w);
        ((float4*)dst)[i] = v;
    }
}

// ---------------------------------------------------------------------------
// Kernel A: QKV projection, cp.async 2-stage double buffer.
// grid = (8192/128, 1024/128, 3), block = 256 (8 warps, warp tile 32x64).
// Reads tf32-rounded g_X / g_W; epilogue writes tf32-rounded Q/K/V + bias.
// ---------------------------------------------------------------------------
#define QKV_STAGE   (128*36 + 32*136)   // floats per stage (As + Bs)
#define QKV_AS_OFF  0
#define QKV_BS_OFF  (128*36)

__global__ __launch_bounds__(256) void qkv_kernel(
    const float* __restrict__ bq,
    const float* __restrict__ bk,
    const float* __restrict__ bv)
{
    extern __shared__ float sm[];

    const float* X = g_X;
    const float* W = g_W[blockIdx.z];
    const float* bias;
    float* dst;
    if (blockIdx.z == 0)      { bias = bq; dst = g_Q; }
    else if (blockIdx.z == 1) { bias = bk; dst = g_K; }
    else                      { bias = bv; dst = g_V; }

    const int m0blk = blockIdx.x * 128;
    const int n0blk = blockIdx.y * 128;
    const int tid  = threadIdx.x;
    const int lane = tid & 31;
    const int warp = tid >> 5;
    const int wm = (warp >> 1) * 32;
    const int wn = (warp & 1) * 64;

    const uint32_t smb = smem_u32(sm);

    // issue loads for k-tile `k` into stage buffer `b`
    auto issue_tile = [&](int k, int b) {
        const uint32_t sb = smb + (uint32_t)(b * QKV_STAGE) * 4u;
#pragma unroll
        for (int i = 0; i < 4; i++) {        // A: 128x32 = 1024 float4, 256 thr
            int f4  = tid + i * 256;
            int row = f4 >> 3;
            int c4  = (f4 & 7) * 4;
            cp_async16(sb + (uint32_t)(QKV_AS_OFF + row * 36 + c4) * 4u,
                       X + (size_t)(m0blk + row) * D_IN + k * 32 + c4);
        }
#pragma unroll
        for (int i = 0; i < 4; i++) {        // B: 32x128 = 1024 float4
            int f4  = tid + i * 256;
            int row = f4 >> 5;
            int c4  = (f4 & 31) * 4;
            cp_async16(sb + (uint32_t)(QKV_BS_OFF + row * 136 + c4) * 4u,
                       W + (size_t)(k * 32 + row) * D_OUT + n0blk + c4);
        }
        cp_commit();
    };

    float c[2][8][4];
#pragma unroll
    for (int mi = 0; mi < 2; mi++)
#pragma unroll
        for (int nb = 0; nb < 8; nb++)
#pragma unroll
            for (int j = 0; j < 4; j++) c[mi][nb][j] = 0.f;

    issue_tile(0, 0);

    const int NK = D_IN / 32;   // 32
    for (int k = 0; k < NK; k++) {
        const int b = k & 1;
        if (k + 1 < NK) { issue_tile(k + 1, (k + 1) & 1); cp_wait<1>(); }
        else            { cp_wait<0>(); }
        __syncthreads();

        const float* As = sm + b * QKV_STAGE + QKV_AS_OFF;
        const float* Bs = sm + b * QKV_STAGE + QKV_BS_OFF;

#pragma unroll
        for (int ks = 0; ks < 4; ks++) {
            uint32_t a[2][4];
#pragma unroll
            for (int mi = 0; mi < 2; mi++) {
                int r  = wm + mi * 16 + (lane >> 2);
                int cc = ks * 8 + (lane & 3);
                a[mi][0] = __float_as_uint(As[r * 36 + cc]);
                a[mi][1] = __float_as_uint(As[(r + 8) * 36 + cc]);
                a[mi][2] = __float_as_uint(As[r * 36 + cc + 4]);
                a[mi][3] = __float_as_uint(As[(r + 8) * 36 + cc + 4]);
            }
#pragma unroll
            for (int nb = 0; nb < 8; nb++) {
                int col = wn + nb * 8 + (lane >> 2);
                int kr  = ks * 8 + (lane & 3);
                uint32_t b0 = __float_as_uint(Bs[kr * 136 + col]);
                uint32_t b1 = __float_as_uint(Bs[(kr + 4) * 136 + col]);
                mma_tf32(c[0][nb][0], c[0][nb][1], c[0][nb][2], c[0][nb][3],
                         a[0][0], a[0][1], a[0][2], a[0][3], b0, b1);
                mma_tf32(c[1][nb][0], c[1][nb][1], c[1][nb][2], c[1][nb][3],
                         a[1][0], a[1][1], a[1][2], a[1][3], b0, b1);
            }
        }
        __syncthreads();    // all reads of stage b done before it is refilled
    }

    // epilogue: bias, tf32-round, scatter to [B,H,T,HD]
#pragma unroll
    for (int mi = 0; mi < 2; mi++) {
#pragma unroll
        for (int nb = 0; nb < 8; nb++) {
            int row = m0blk + wm + mi * 16 + (lane >> 2);
            int col = n0blk + wn + nb * 8 + 2 * (lane & 3);
            int b_ = row >> 11;
            int t_ = row & 2047;
            int h  = col >> 6;
            int d  = col & 63;
            float bv0 = bias[col];
            float bv1 = bias[col + 1];
            size_t base = (((size_t)(b_ * NH + h)) * TT) * HD;
            float2 v0 = make_float2(to_tf32(c[mi][nb][0] + bv0), to_tf32(c[mi][nb][1] + bv1));
            float2 v1 = make_float2(to_tf32(c[mi][nb][2] + bv0), to_tf32(c[mi][nb][3] + bv1));
            *(float2*)(dst + base + (size_t)t_ * HD + d)       = v0;
            *(float2*)(dst + base + (size_t)(t_ + 8) * HD + d) = v1;
        }
    }
}

// ---------------------------------------------------------------------------
// Kernel B: causal flash attention, cp.async double-buffered KV tiles.
// 1D grid of 2048, longest tiles first. block = 128 (4 warps x 16 q-rows).
// smem: sK[2] | sV[2], each 64x68 floats. P reuses current sK buffer.
// ---------------------------------------------------------------------------
#define ATT_TILE  (64*68)

__global__ __launch_bounds__(128) void attn_kernel(float* __restrict__ out)
{
    extern __shared__ float sm[];
    // layout: sK0 | sK1 | sV0 | sV1
    const int tid = threadIdx.x;
    const int lane = tid & 31;
    const int warp = tid >> 5;

    const int bid = blockIdx.x;
    const int qt  = (TT/64 - 1) - (bid >> 6);   // longest first
    const int bh  = bid & 63;

    const float* Qb = g_Q + (size_t)bh * TT * HD;
    const float* Kb = g_K + (size_t)bh * TT * HD;
    const float* Vb = g_V + (size_t)bh * TT * HD;

    const int q0 = qt * 64;
    const uint32_t smb = smem_u32(sm);

    // issue cp.async for KV tile kt into buffer b
    auto issue_kv = [&](int kt, int b) {
        const uint32_t kdst = smb + (uint32_t)(b * ATT_TILE) * 4u;
        const uint32_t vdst = smb + (uint32_t)((2 + b) * ATT_TILE) * 4u;
#pragma unroll
        for (int i = 0; i < 8; i++) {
            int f4  = tid + i * 128;
            int row = f4 >> 4;
            int c4  = (f4 & 15) * 4;
            size_t g = (size_t)(kt * 64 + row) * HD + c4;
            uint32_t so = (uint32_t)(row * 68 + c4) * 4u;
            cp_async16(kdst + so, Kb + g);
            cp_async16(vdst + so, Vb + g);
        }
        cp_commit();
    };

    // prologue: start tile 0 load, stage Q into sK1 region meanwhile.
    // Q tile is 64 rows x 64 cols = 1024 float4 -> 8 iterations of 128 threads.
    issue_kv(0, 0);
    {
        float* sQ = sm + 1 * ATT_TILE;   // sK1 (free until tile 1 prefetch)
#pragma unroll
        for (int i = 0; i < 8; i++) {
            int f4  = tid + i * 128;
            int row = f4 >> 4;
            int c4  = (f4 & 15) * 4;
            float4 v = *(const float4*)(Qb + (size_t)(q0 + row) * HD + c4);
            *(float4*)(sQ + row * 68 + c4) = v;   // already tf32-rounded in gmem
        }
    }
    __syncthreads();

    uint32_t qa[8][4];
    {
        const float* sQ = sm + 1 * ATT_TILE;
        int r = warp * 16 + (lane >> 2);
#pragma unroll
        for (int ks = 0; ks < 8; ks++) {
            int cc = ks * 8 + (lane & 3);
            qa[ks][0] = __float_as_uint(sQ[r * 68 + cc]);
            qa[ks][1] = __float_as_uint(sQ[(r + 8) * 68 + cc]);
            qa[ks][2] = __float_as_uint(sQ[r * 68 + cc + 4]);
            qa[ks][3] = __float_as_uint(sQ[(r + 8) * 68 + cc + 4]);
        }
    }

    float o[8][4];
#pragma unroll
    for (int nb = 0; nb < 8; nb++)
#pragma unroll
        for (int j = 0; j < 4; j++) o[nb][j] = 0.f;
    float m0 = -1e30f, m1 = -1e30f, l0 = 0.f, l1 = 0.f;

    const int qrow0 = q0 + warp * 16 + (lane >> 2);
    const int qrow1 = qrow0 + 8;

    for (int kt = 0; kt <= qt; kt++) {
        const int b = kt & 1;
        __syncthreads();   // prev iter's P/V reads (and Q frag reads) complete
        if (kt + 1 <= qt) { issue_kv(kt + 1, (kt + 1) & 1); cp_wait<1>(); }
        else              { cp_wait<0>(); }
        __syncthreads();   // tile kt visible to all warps

        float* sK = sm + b * ATT_TILE;
        float* sV = sm + (2 + b) * ATT_TILE;

        // S = Q * K^T
        float s[8][4];
#pragma unroll
        for (int nb = 0; nb < 8; nb++)
#pragma unroll
            for (int j = 0; j < 4; j++) s[nb][j] = 0.f;

#pragma unroll
        for (int ks = 0; ks < 8; ks++) {
#pragma unroll
            for (int nb = 0; nb < 8; nb++) {
                int n  = nb * 8 + (lane >> 2);
                int kk = ks * 8 + (lane & 3);
                uint32_t b0 = __float_as_uint(sK[n * 68 + kk]);
                uint32_t b1 = __float_as_uint(sK[n * 68 + kk + 4]);
                mma_tf32(s[nb][0], s[nb][1], s[nb][2], s[nb][3],
                         qa[ks][0], qa[ks][1], qa[ks][2], qa[ks][3], b0, b1);
            }
        }

        // scale, causal mask, online softmax
        const bool diag = (kt == qt);
        float tm0 = -1e30f, tm1 = -1e30f;
#pragma unroll
        for (int nb = 0; nb < 8; nb++) {
            int kv = kt * 64 + nb * 8 + 2 * (lane & 3);
            s[nb][0] *= 0.125f; if (diag && kv     > qrow0) s[nb][0] = -1e30f;
            s[nb][1] *= 0.125f; if (diag && kv + 1 > qrow0) s[nb][1] = -1e30f;
            s[nb][2] *= 0.125f; if (diag && kv     > qrow1) s[nb][2] = -1e30f;
            s[nb][3] *= 0.125f; if (diag && kv + 1 > qrow1) s[nb][3] = -1e30f;
            tm0 = fmaxf(tm0, fmaxf(s[nb][0], s[nb][1]));
            tm1 = fmaxf(tm1, fmaxf(s[nb][2], s[nb][3]));
        }
        tm0 = fmaxf(tm0, __shfl_xor_sync(0xffffffffu, tm0, 1));
        tm0 = fmaxf(tm0, __shfl_xor_sync(0xffffffffu, tm0, 2));
        tm1 = fmaxf(tm1, __shfl_xor_sync(0xffffffffu, tm1, 1));
        tm1 = fmaxf(tm1, __shfl_xor_sync(0xffffffffu, tm1, 2));

        float mn0 = fmaxf(m0, tm0), mn1 = fmaxf(m1, tm1);
        float al0 = __expf(m0 - mn0), al1 = __expf(m1 - mn1);
        float rs0 = 0.f, rs1 = 0.f;
#pragma unroll
        for (int nb = 0; nb < 8; nb++) {
            s[nb][0] = __expf(s[nb][0] - mn0); rs0 += s[nb][0];
            s[nb][1] = __expf(s[nb][1] - mn0); rs0 += s[nb][1];
            s[nb][2] = __expf(s[nb][2] - mn1); rs1 += s[nb][2];
            s[nb][3] = __expf(s[nb][3] - mn1); rs1 += s[nb][3];
            o[nb][0] *= al0; o[nb][1] *= al0;
            o[nb][2] *= al1; o[nb][3] *= al1;
        }
        rs0 += __shfl_xor_sync(0xffffffffu, rs0, 1);
        rs0 += __shfl_xor_sync(0xffffffffu, rs0, 2);
        rs1 += __shfl_xor_sync(0xffffffffu, rs1, 1);
        rs1 += __shfl_xor_sync(0xffffffffu, rs1, 2);
        l0 = l0 * al0 + rs0;
        l1 = l1 * al1 + rs1;
        m0 = mn0; m1 = mn1;

        __syncthreads();   // all warps done reading K before P overwrites it
        {
            int r = warp * 16 + (lane >> 2);
#pragma unroll
            for (int nb = 0; nb < 8; nb++) {
                int cc = nb * 8 + 2 * (lane & 3);
                sK[r * 68 + cc]           = to_tf32(s[nb][0]);
                sK[r * 68 + cc + 1]       = to_tf32(s[nb][1]);
                sK[(r + 8) * 68 + cc]     = to_tf32(s[nb][2]);
                sK[(r + 8) * 68 + cc + 1] = to_tf32(s[nb][3]);
            }
        }
        __syncwarp();

        // O += P * V
        {
            int r = warp * 16 + (lane >> 2);
#pragma unroll
            for (int kc = 0; kc < 8; kc++) {
                int cc = kc * 8 + (lane & 3);
                uint32_t pa0 = __float_as_uint(sK[r * 68 + cc]);
                uint32_t pa1 = __float_as_uint(sK[(r + 8) * 68 + cc]);
                uint32_t pa2 = __float_as_uint(sK[r * 68 + cc + 4]);
                uint32_t pa3 = __float_as_uint(sK[(r + 8) * 68 + cc + 4]);
#pragma unroll
                for (int nb = 0; nb < 8; nb++) {
                    int d  = nb * 8 + (lane >> 2);
                    int kk = kc * 8 + (lane & 3);
                    uint32_t vb0 = __float_as_uint(sV[kk * 68 + d]);
                    uint32_t vb1 = __float_as_uint(sV[(kk + 4) * 68 + d]);
                    mma_tf32(o[nb][0], o[nb][1], o[nb][2], o[nb][3],
                             pa0, pa1, pa2, pa3, vb0, vb1);
                }
            }
        }
    }

    // normalize and write out[b, t, h*64 + d]
    float inv0 = 1.f / l0;
    float inv1 = 1.f / l1;
    int b_ = bh >> 4;
    int h  = bh & 15;
    float* orow0 = out + ((size_t)b_ * TT + qrow0) * D_OUT + h * HD;
    float* orow1 = out + ((size_t)b_ * TT + qrow1) * D_OUT + h * HD;
#pragma unroll
    for (int nb = 0; nb < 8; nb++) {
        int cc = nb * 8 + 2 * (lane & 3);
        *(float2*)(orow0 + cc) = make_float2(o[nb][0] * inv0, o[nb][1] * inv0);
        *(float2*)(orow1 + cc) = make_float2(o[nb][2] * inv1, o[nb][3] * inv1);
    }
}

// ---------------------------------------------------------------------------
extern "C" void kernel_launch(void* const* d_in, const int* in_sizes, int n_in,
                              void* d_out, int out_size)
{
    const float* X  = (const float*)d_in[0];
    const float* Wq = (const float*)d_in[1];
    const float* bq = (const float*)d_in[2];
    const float* Wk = (const float*)d_in[3];
    const float* bk = (const float*)d_in[4];
    const float* Wv = (const float*)d_in[5];
    const float* bv = (const float*)d_in[6];
    float* out = (float*)d_out;

    // idempotent attribute setup (same values every call; no behavior change)
    cudaFuncSetAttribute(qkv_kernel, cudaFuncAttributeMaxDynamicSharedMemorySize,
                         2 * QKV_STAGE * (int)sizeof(float));
    cudaFuncSetAttribute(attn_kernel, cudaFuncAttributeMaxDynamicSharedMemorySize,
                         4 * ATT_TILE * (int)sizeof(float));

    // device-symbol addresses (host-side lookup, no allocation)
    float* dX; cudaGetSymbolAddress((void**)&dX, g_X);
    float* dW; cudaGetSymbolAddress((void**)&dW, g_W);

    prep_kernel<<<256, 256>>>(X,  dX,                 NROWS*D_IN/4);
    prep_kernel<<<256, 256>>>(Wq, dW + 0*D_IN*D_OUT,  D_IN*D_OUT/4);
    prep_kernel<<<256, 256>>>(Wk, dW + 1*D_IN*D_OUT,  D_IN*D_OUT/4);
    prep_kernel<<<256, 256>>>(Wv, dW + 2*D_IN*D_OUT,  D_IN*D_OUT/4);

    dim3 gA(NROWS / 128, D_OUT / 128, 3);
    qkv_kernel<<<gA, 256, 2 * QKV_STAGE * sizeof(float)>>>(bq, bk, bv);

    attn_kernel<<<(TT/64) * BB * NH, 128, 4 * ATT_TILE * sizeof(float)>>>(out);
}

// round 7
// speedup vs baseline: 1.2063x; 1.1061x over previous
#include <cuda_runtime.h>
#include <cstdint>

#define D_IN   1024
#define D_OUT  1024
#define NH     16
#define HD     64
#define BB     4
#define TT     2048
#define NROWS  (BB*TT)   // 8192

// ---------------------------------------------------------------------------
// Scratch (static __device__ per allocation-guard rules)
// ---------------------------------------------------------------------------
__device__ float g_Q[BB*NH*TT*HD];
__device__ float g_K[BB*NH*TT*HD];
__device__ float g_V[BB*NH*TT*HD];
__device__ float g_X[NROWS*D_IN];          // tf32-rounded copy of inputs
__device__ float g_W[3][D_IN*D_OUT];       // tf32-rounded copies of Wq,Wk,Wv

__device__ __forceinline__ float to_tf32(float x) {
    uint32_t u;
    asm("cvt.rna.tf32.f32 %0, %1;" : "=r"(u) : "f"(x));
    return __uint_as_float(u);
}

__device__ __forceinline__ void mma_tf32(float& c0, float& c1, float& c2, float& c3,
                                         uint32_t a0, uint32_t a1, uint32_t a2, uint32_t a3,
                                         uint32_t b0, uint32_t b1) {
    asm volatile(
        "mma.sync.aligned.m16n8k8.row.col.f32.tf32.tf32.f32 "
        "{%0,%1,%2,%3}, {%4,%5,%6,%7}, {%8,%9}, {%0,%1,%2,%3};\n"
        : "+f"(c0), "+f"(c1), "+f"(c2), "+f"(c3)
        : "r"(a0), "r"(a1), "r"(a2), "r"(a3), "r"(b0), "r"(b1));
}

__device__ __forceinline__ uint32_t smem_u32(const void* p) {
    return (uint32_t)__cvta_generic_to_shared(p);
}
__device__ __forceinline__ void cp_async16(uint32_t dst, const void* src) {
    asm volatile("cp.async.cg.shared.global [%0], [%1], 16;" :: "r"(dst), "l"(src));
}
__device__ __forceinline__ void cp_commit() {
    asm volatile("cp.async.commit_group;");
}
template <int N>
__device__ __forceinline__ void cp_wait() {
    asm volatile("cp.async.wait_group %0;" :: "n"(N));
}

// ---------------------------------------------------------------------------
// Kernel 0: tf32-round inputs into scratch (grid-stride, float4)
// ---------------------------------------------------------------------------
__global__ void prep_kernel(const float* __restrict__ src, float* __restrict__ dst, int n4)
{
    int i = blockIdx.x * blockDim.x + threadIdx.x;
    int stride = gridDim.x * blockDim.x;
    for (; i < n4; i += stride) {
        float4 v = ((const float4*)src)[i];
        v.x = to_tf32(v.x); v.y = to_tf32(v.y); v.z = to_tf32(v.z); v.w = to_tf32(v.w);
        ((float4*)dst)[i] = v;
    }
}

// ---------------------------------------------------------------------------
// Kernel A: QKV projection, cp.async 2-stage double buffer. (unchanged)
// ---------------------------------------------------------------------------
#define QKV_STAGE   (128*36 + 32*136)
#define QKV_AS_OFF  0
#define QKV_BS_OFF  (128*36)

__global__ __launch_bounds__(256) void qkv_kernel(
    const float* __restrict__ bq,
    const float* __restrict__ bk,
    const float* __restrict__ bv)
{
    extern __shared__ float sm[];

    const float* X = g_X;
    const float* W = g_W[blockIdx.z];
    const float* bias;
    float* dst;
    if (blockIdx.z == 0)      { bias = bq; dst = g_Q; }
    else if (blockIdx.z == 1) { bias = bk; dst = g_K; }
    else                      { bias = bv; dst = g_V; }

    const int m0blk = blockIdx.x * 128;
    const int n0blk = blockIdx.y * 128;
    const int tid  = threadIdx.x;
    const int lane = tid & 31;
    const int warp = tid >> 5;
    const int wm = (warp >> 1) * 32;
    const int wn = (warp & 1) * 64;

    const uint32_t smb = smem_u32(sm);

    auto issue_tile = [&](int k, int b) {
        const uint32_t sb = smb + (uint32_t)(b * QKV_STAGE) * 4u;
#pragma unroll
        for (int i = 0; i < 4; i++) {
            int f4  = tid + i * 256;
            int row = f4 >> 3;
            int c4  = (f4 & 7) * 4;
            cp_async16(sb + (uint32_t)(QKV_AS_OFF + row * 36 + c4) * 4u,
                       X + (size_t)(m0blk + row) * D_IN + k * 32 + c4);
        }
#pragma unroll
        for (int i = 0; i < 4; i++) {
            int f4  = tid + i * 256;
            int row = f4 >> 5;
            int c4  = (f4 & 31) * 4;
            cp_async16(sb + (uint32_t)(QKV_BS_OFF + row * 136 + c4) * 4u,
                       W + (size_t)(k * 32 + row) * D_OUT + n0blk + c4);
        }
        cp_commit();
    };

    float c[2][8][4];
#pragma unroll
    for (int mi = 0; mi < 2; mi++)
#pragma unroll
        for (int nb = 0; nb < 8; nb++)
#pragma unroll
            for (int j = 0; j < 4; j++) c[mi][nb][j] = 0.f;

    issue_tile(0, 0);

    const int NK = D_IN / 32;
    for (int k = 0; k < NK; k++) {
        const int b = k & 1;
        if (k + 1 < NK) { issue_tile(k + 1, (k + 1) & 1); cp_wait<1>(); }
        else            { cp_wait<0>(); }
        __syncthreads();

        const float* As = sm + b * QKV_STAGE + QKV_AS_OFF;
        const float* Bs = sm + b * QKV_STAGE + QKV_BS_OFF;

#pragma unroll
        for (int ks = 0; ks < 4; ks++) {
            uint32_t a[2][4];
#pragma unroll
            for (int mi = 0; mi < 2; mi++) {
                int r  = wm + mi * 16 + (lane >> 2);
                int cc = ks * 8 + (lane & 3);
                a[mi][0] = __float_as_uint(As[r * 36 + cc]);
                a[mi][1] = __float_as_uint(As[(r + 8) * 36 + cc]);
                a[mi][2] = __float_as_uint(As[r * 36 + cc + 4]);
                a[mi][3] = __float_as_uint(As[(r + 8) * 36 + cc + 4]);
            }
#pragma unroll
            for (int nb = 0; nb < 8; nb++) {
                int col = wn + nb * 8 + (lane >> 2);
                int kr  = ks * 8 + (lane & 3);
                uint32_t b0 = __float_as_uint(Bs[kr * 136 + col]);
                uint32_t b1 = __float_as_uint(Bs[(kr + 4) * 136 + col]);
                mma_tf32(c[0][nb][0], c[0][nb][1], c[0][nb][2], c[0][nb][3],
                         a[0][0], a[0][1], a[0][2], a[0][3], b0, b1);
                mma_tf32(c[1][nb][0], c[1][nb][1], c[1][nb][2], c[1][nb][3],
                         a[1][0], a[1][1], a[1][2], a[1][3], b0, b1);
            }
        }
        __syncthreads();
    }

#pragma unroll
    for (int mi = 0; mi < 2; mi++) {
#pragma unroll
        for (int nb = 0; nb < 8; nb++) {
            int row = m0blk + wm + mi * 16 + (lane >> 2);
            int col = n0blk + wn + nb * 8 + 2 * (lane & 3);
            int b_ = row >> 11;
            int t_ = row & 2047;
            int h  = col >> 6;
            int d  = col & 63;
            float bv0 = bias[col];
            float bv1 = bias[col + 1];
            size_t base = (((size_t)(b_ * NH + h)) * TT) * HD;
            float2 v0 = make_float2(to_tf32(c[mi][nb][0] + bv0), to_tf32(c[mi][nb][1] + bv1));
            float2 v1 = make_float2(to_tf32(c[mi][nb][2] + bv0), to_tf32(c[mi][nb][3] + bv1));
            *(float2*)(dst + base + (size_t)t_ * HD + d)       = v0;
            *(float2*)(dst + base + (size_t)(t_ + 8) * HD + d) = v1;
        }
    }
}

// ---------------------------------------------------------------------------
// Kernel B: causal flash attention, 128 q-rows per CTA (4 warps x 32 rows).
// KV tiles of 64, cp.async double-buffered. Dedicated smem P buffer
// (warp-private rows -> no barrier before P store).
// grid = 16*64 = 1024, longest q-tiles first. block = 128.
// smem: K0|K1|V0|V1 (64x68 each) | P (128x68)
// ---------------------------------------------------------------------------
#define KV_TILE   (64*68)
#define P_OFF     (4*KV_TILE)
#define ATT_SMEMF (4*KV_TILE + 128*68)

__global__ __launch_bounds__(128) void attn_kernel(float* __restrict__ out)
{
    extern __shared__ float sm[];
    const int tid  = threadIdx.x;
    const int lane = tid & 31;
    const int warp = tid >> 5;

    const int bid = blockIdx.x;
    const int qt  = (TT/128 - 1) - (bid >> 6);   // 15..0, longest first
    const int bh  = bid & 63;

    const float* Qb = g_Q + (size_t)bh * TT * HD;
    const float* Kb = g_K + (size_t)bh * TT * HD;
    const float* Vb = g_V + (size_t)bh * TT * HD;

    const int q0 = qt * 128;
    const int ktmax = 2 * qt + 1;
    const uint32_t smb = smem_u32(sm);
    float* sP = sm + P_OFF;

    auto issue_kv = [&](int kt, int b) {
        const uint32_t kdst = smb + (uint32_t)(b * KV_TILE) * 4u;
        const uint32_t vdst = smb + (uint32_t)((2 + b) * KV_TILE) * 4u;
#pragma unroll
        for (int i = 0; i < 8; i++) {
            int f4  = tid + i * 128;
            int row = f4 >> 4;
            int c4  = (f4 & 15) * 4;
            size_t g = (size_t)(kt * 64 + row) * HD + c4;
            uint32_t so = (uint32_t)(row * 68 + c4) * 4u;
            cp_async16(kdst + so, Kb + g);
            cp_async16(vdst + so, Vb + g);
        }
        cp_commit();
    };

    // prologue: start tile 0; stage Q (128x64) into sP, then pull A-fragments
    issue_kv(0, 0);
#pragma unroll
    for (int i = 0; i < 16; i++) {
        int f4  = tid + i * 128;
        int row = f4 >> 4;
        int c4  = (f4 & 15) * 4;
        float4 v = *(const float4*)(Qb + (size_t)(q0 + row) * HD + c4);
        *(float4*)(sP + row * 68 + c4) = v;   // already tf32-rounded in gmem
    }
    __syncthreads();

    uint32_t qa[2][8][4];
#pragma unroll
    for (int mi = 0; mi < 2; mi++) {
        int r = warp * 32 + mi * 16 + (lane >> 2);
#pragma unroll
        for (int ks = 0; ks < 8; ks++) {
            int cc = ks * 8 + (lane & 3);
            qa[mi][ks][0] = __float_as_uint(sP[r * 68 + cc]);
            qa[mi][ks][1] = __float_as_uint(sP[(r + 8) * 68 + cc]);
            qa[mi][ks][2] = __float_as_uint(sP[r * 68 + cc + 4]);
            qa[mi][ks][3] = __float_as_uint(sP[(r + 8) * 68 + cc + 4]);
        }
    }

    float o[2][8][4];
#pragma unroll
    for (int mi = 0; mi < 2; mi++)
#pragma unroll
        for (int nb = 0; nb < 8; nb++)
#pragma unroll
            for (int j = 0; j < 4; j++) o[mi][nb][j] = 0.f;
    float m_[2][2] = {{-1e30f, -1e30f}, {-1e30f, -1e30f}};
    float l_[2][2] = {{0.f, 0.f}, {0.f, 0.f}};

    const int wrow = q0 + warp * 32 + (lane >> 2);   // base row of this thread

    for (int kt = 0; kt <= ktmax; kt++) {
        const int b = kt & 1;
        __syncthreads();   // everyone done reading buffer (kt+1)&1 from tile kt-1
        if (kt + 1 <= ktmax) { issue_kv(kt + 1, (kt + 1) & 1); cp_wait<1>(); }
        else                 { cp_wait<0>(); }
        __syncthreads();   // tile kt visible to all warps

        // warp fully masked on last tile? (all 32 rows < first kv index)
        if (kt * 64 > q0 + warp * 32 + 31) continue;

        float* sK = sm + b * KV_TILE;
        float* sV = sm + (2 + b) * KV_TILE;

        // S = Q * K^T (32 rows x 64 kv per warp)
        float s[2][8][4];
#pragma unroll
        for (int mi = 0; mi < 2; mi++)
#pragma unroll
            for (int nb = 0; nb < 8; nb++)
#pragma unroll
                for (int j = 0; j < 4; j++) s[mi][nb][j] = 0.f;

#pragma unroll
        for (int ks = 0; ks < 8; ks++) {
#pragma unroll
            for (int nb = 0; nb < 8; nb++) {
                int n  = nb * 8 + (lane >> 2);
                int kk = ks * 8 + (lane & 3);
                uint32_t b0 = __float_as_uint(sK[n * 68 + kk]);
                uint32_t b1 = __float_as_uint(sK[n * 68 + kk + 4]);
                mma_tf32(s[0][nb][0], s[0][nb][1], s[0][nb][2], s[0][nb][3],
                         qa[0][ks][0], qa[0][ks][1], qa[0][ks][2], qa[0][ks][3], b0, b1);
                mma_tf32(s[1][nb][0], s[1][nb][1], s[1][nb][2], s[1][nb][3],
                         qa[1][ks][0], qa[1][ks][1], qa[1][ks][2], qa[1][ks][3], b0, b1);
            }
        }

        // scale, causal mask, online softmax (4 row groups: mi x {lo,hi})
        const bool diag = (kt >= 2 * qt);
#pragma unroll
        for (int mi = 0; mi < 2; mi++) {
            const int r0 = wrow + mi * 16;       // rows for c0/c1
            const int r1 = r0 + 8;               // rows for c2/c3
            float tm0 = -1e30f, tm1 = -1e30f;
#pragma unroll
            for (int nb = 0; nb < 8; nb++) {
                int kv = kt * 64 + nb * 8 + 2 * (lane & 3);
                s[mi][nb][0] *= 0.125f; if (diag && kv     > r0) s[mi][nb][0] = -1e30f;
                s[mi][nb][1] *= 0.125f; if (diag && kv + 1 > r0) s[mi][nb][1] = -1e30f;
                s[mi][nb][2] *= 0.125f; if (diag && kv     > r1) s[mi][nb][2] = -1e30f;
                s[mi][nb][3] *= 0.125f; if (diag && kv + 1 > r1) s[mi][nb][3] = -1e30f;
                tm0 = fmaxf(tm0, fmaxf(s[mi][nb][0], s[mi][nb][1]));
                tm1 = fmaxf(tm1, fmaxf(s[mi][nb][2], s[mi][nb][3]));
            }
            tm0 = fmaxf(tm0, __shfl_xor_sync(0xffffffffu, tm0, 1));
            tm0 = fmaxf(tm0, __shfl_xor_sync(0xffffffffu, tm0, 2));
            tm1 = fmaxf(tm1, __shfl_xor_sync(0xffffffffu, tm1, 1));
            tm1 = fmaxf(tm1, __shfl_xor_sync(0xffffffffu, tm1, 2));

            float mn0 = fmaxf(m_[mi][0], tm0), mn1 = fmaxf(m_[mi][1], tm1);
            float al0 = __expf(m_[mi][0] - mn0), al1 = __expf(m_[mi][1] - mn1);
            float rs0 = 0.f, rs1 = 0.f;
#pragma unroll
            for (int nb = 0; nb < 8; nb++) {
                s[mi][nb][0] = __expf(s[mi][nb][0] - mn0); rs0 += s[mi][nb][0];
                s[mi][nb][1] = __expf(s[mi][nb][1] - mn0); rs0 += s[mi][nb][1];
                s[mi][nb][2] = __expf(s[mi][nb][2] - mn1); rs1 += s[mi][nb][2];
                s[mi][nb][3] = __expf(s[mi][nb][3] - mn1); rs1 += s[mi][nb][3];
                o[mi][nb][0] *= al0; o[mi][nb][1] *= al0;
                o[mi][nb][2] *= al1; o[mi][nb][3] *= al1;
            }
            rs0 += __shfl_xor_sync(0xffffffffu, rs0, 1);
            rs0 += __shfl_xor_sync(0xffffffffu, rs0, 2);
            rs1 += __shfl_xor_sync(0xffffffffu, rs1, 1);
            rs1 += __shfl_xor_sync(0xffffffffu, rs1, 2);
            l_[mi][0] = l_[mi][0] * al0 + rs0;
            l_[mi][1] = l_[mi][1] * al1 + rs1;
            m_[mi][0] = mn0; m_[mi][1] = mn1;
        }

        // store P into warp-private rows of sP (no block barrier needed)
#pragma unroll
        for (int mi = 0; mi < 2; mi++) {
            int r = warp * 32 + mi * 16 + (lane >> 2);
#pragma unroll
            for (int nb = 0; nb < 8; nb++) {
                int cc = nb * 8 + 2 * (lane & 3);
                sP[r * 68 + cc]           = to_tf32(s[mi][nb][0]);
                sP[r * 68 + cc + 1]       = to_tf32(s[mi][nb][1]);
                sP[(r + 8) * 68 + cc]     = to_tf32(s[mi][nb][2]);
                sP[(r + 8) * 68 + cc + 1] = to_tf32(s[mi][nb][3]);
            }
        }
        __syncwarp();

        // O += P * V
#pragma unroll
        for (int kc = 0; kc < 8; kc++) {
            uint32_t pa[2][4];
#pragma unroll
            for (int mi = 0; mi < 2; mi++) {
                int r  = warp * 32 + mi * 16 + (lane >> 2);
                int cc = kc * 8 + (lane & 3);
                pa[mi][0] = __float_as_uint(sP[r * 68 + cc]);
                pa[mi][1] = __float_as_uint(sP[(r + 8) * 68 + cc]);
                pa[mi][2] = __float_as_uint(sP[r * 68 + cc + 4]);
                pa[mi][3] = __float_as_uint(sP[(r + 8) * 68 + cc + 4]);
            }
#pragma unroll
            for (int nb = 0; nb < 8; nb++) {
                int d  = nb * 8 + (lane >> 2);
                int kk = kc * 8 + (lane & 3);
                uint32_t vb0 = __float_as_uint(sV[kk * 68 + d]);
                uint32_t vb1 = __float_as_uint(sV[(kk + 4) * 68 + d]);
                mma_tf32(o[0][nb][0], o[0][nb][1], o[0][nb][2], o[0][nb][3],
                         pa[0][0], pa[0][1], pa[0][2], pa[0][3], vb0, vb1);
                mma_tf32(o[1][nb][0], o[1][nb][1], o[1][nb][2], o[1][nb][3],
                         pa[1][0], pa[1][1], pa[1][2], pa[1][3], vb0, vb1);
            }
        }
        __syncwarp();   // P reads done before next tile's P store
    }

    // normalize and write out[b, t, h*64 + d]
    const int b_ = bh >> 4;
    const int h  = bh & 15;
#pragma unroll
    for (int mi = 0; mi < 2; mi++) {
        float inv0 = 1.f / l_[mi][0];
        float inv1 = 1.f / l_[mi][1];
        int r0 = wrow + mi * 16;
        float* orow0 = out + ((size_t)b_ * TT + r0) * D_OUT + h * HD;
        float* orow1 = out + ((size_t)b_ * TT + r0 + 8) * D_OUT + h * HD;
#pragma unroll
        for (int nb = 0; nb < 8; nb++) {
            int cc = nb * 8 + 2 * (lane & 3);
            *(float2*)(orow0 + cc) = make_float2(o[mi][nb][0] * inv0, o[mi][nb][1] * inv0);
            *(float2*)(orow1 + cc) = make_float2(o[mi][nb][2] * inv1, o[mi][nb][3] * inv1);
        }
    }
}

// ---------------------------------------------------------------------------
extern "C" void kernel_launch(void* const* d_in, const int* in_sizes, int n_in,
                              void* d_out, int out_size)
{
    const float* X  = (const float*)d_in[0];
    const float* Wq = (const float*)d_in[1];
    const float* bq = (const float*)d_in[2];
    const float* Wk = (const float*)d_in[3];
    const float* bk = (const float*)d_in[4];
    const float* Wv = (const float*)d_in[5];
    const float* bv = (const float*)d_in[6];
    float* out = (float*)d_out;

    cudaFuncSetAttribute(qkv_kernel, cudaFuncAttributeMaxDynamicSharedMemorySize,
                         2 * QKV_STAGE * (int)sizeof(float));
    cudaFuncSetAttribute(attn_kernel, cudaFuncAttributeMaxDynamicSharedMemorySize,
                         ATT_SMEMF * (int)sizeof(float));

    float* dX; cudaGetSymbolAddress((void**)&dX, g_X);
    float* dW; cudaGetSymbolAddress((void**)&dW, g_W);

    prep_kernel<<<1024, 256>>>(X,  dX,                 NROWS*D_IN/4);
    prep_kernel<<<1024, 256>>>(Wq, dW + 0*D_IN*D_OUT,  D_IN*D_OUT/4);
    prep_kernel<<<1024, 256>>>(Wk, dW + 1*D_IN*D_OUT,  D_IN*D_OUT/4);
    prep_kernel<<<1024, 256>>>(Wv, dW + 2*D_IN*D_OUT,  D_IN*D_OUT/4);

    dim3 gA(NROWS / 128, D_OUT / 128, 3);
    qkv_kernel<<<gA, 256, 2 * QKV_STAGE * sizeof(float)>>>(bq, bk, bv);

    attn_kernel<<<(TT/128) * BB * NH, 128, ATT_SMEMF * sizeof(float)>>>(out);
}

// round 8
// speedup vs baseline: 1.2126x; 1.0052x over previous
#include <cuda_runtime.h>
#include <cstdint>

#define D_IN   1024
#define D_OUT  1024
#define NH     16
#define HD     64
#define BB     4
#define TT     2048
#define NROWS  (BB*TT)   // 8192

// ---------------------------------------------------------------------------
// Scratch (static __device__ per allocation-guard rules)
// Q, K: [bh][t][d']  (d' = head-dim with 8-group pair permutation)
// V   : [bh][d][t']  (transposed, t' permuted within 8-groups)
// ---------------------------------------------------------------------------
__device__ float g_Q[BB*NH*TT*HD];
__device__ float g_K[BB*NH*TT*HD];
__device__ float g_V[BB*NH*TT*HD];
__device__ float g_X[NROWS*D_IN];
__device__ float g_W[3][D_IN*D_OUT];

// pair permutation within an 8-group: z -> (z&3)*2 + (z>>2)
// maps logical (z, z+4) -> physical (2z, 2z+1): fragment pairs become LDS.64
__device__ __forceinline__ int perm8(int z) { return ((z & 3) << 1) | (z >> 2); }

__device__ __forceinline__ float to_tf32(float x) {
    uint32_t u;
    asm("cvt.rna.tf32.f32 %0, %1;" : "=r"(u) : "f"(x));
    return __uint_as_float(u);
}

__device__ __forceinline__ void mma_tf32(float& c0, float& c1, float& c2, float& c3,
                                         uint32_t a0, uint32_t a1, uint32_t a2, uint32_t a3,
                                         uint32_t b0, uint32_t b1) {
    asm volatile(
        "mma.sync.aligned.m16n8k8.row.col.f32.tf32.tf32.f32 "
        "{%0,%1,%2,%3}, {%4,%5,%6,%7}, {%8,%9}, {%0,%1,%2,%3};\n"
        : "+f"(c0), "+f"(c1), "+f"(c2), "+f"(c3)
        : "r"(a0), "r"(a1), "r"(a2), "r"(a3), "r"(b0), "r"(b1));
}

__device__ __forceinline__ uint32_t smem_u32(const void* p) {
    return (uint32_t)__cvta_generic_to_shared(p);
}
__device__ __forceinline__ void cp_async16(uint32_t dst, const void* src) {
    asm volatile("cp.async.cg.shared.global [%0], [%1], 16;" :: "r"(dst), "l"(src));
}
__device__ __forceinline__ void cp_commit() {
    asm volatile("cp.async.commit_group;");
}
template <int N>
__device__ __forceinline__ void cp_wait() {
    asm volatile("cp.async.wait_group %0;" :: "n"(N));
}

// ---------------------------------------------------------------------------
// Kernel 0: tf32-round inputs into scratch
// ---------------------------------------------------------------------------
__global__ void prep_kernel(const float* __restrict__ src, float* __restrict__ dst, int n4)
{
    int i = blockIdx.x * blockDim.x + threadIdx.x;
    int stride = gridDim.x * blockDim.x;
    for (; i < n4; i += stride) {
        float4 v = ((const float4*)src)[i];
        v.x = to_tf32(v.x); v.y = to_tf32(v.y); v.z = to_tf32(v.z); v.w = to_tf32(v.w);
        ((float4*)dst)[i] = v;
    }
}

// ---------------------------------------------------------------------------
// Kernel A: QKV projection (cp.async double buffer). Epilogue writes the
// permuted layouts described above.
// ---------------------------------------------------------------------------
#define QKV_STAGE   (128*36 + 32*136)
#define QKV_AS_OFF  0
#define QKV_BS_OFF  (128*36)

__global__ __launch_bounds__(256) void qkv_kernel(
    const float* __restrict__ bq,
    const float* __restrict__ bk,
    const float* __restrict__ bv)
{
    extern __shared__ float sm[];

    const float* X = g_X;
    const float* W = g_W[blockIdx.z];
    const float* bias;
    float* dst;
    if (blockIdx.z == 0)      { bias = bq; dst = g_Q; }
    else if (blockIdx.z == 1) { bias = bk; dst = g_K; }
    else                      { bias = bv; dst = g_V; }

    const int m0blk = blockIdx.x * 128;
    const int n0blk = blockIdx.y * 128;
    const int tid  = threadIdx.x;
    const int lane = tid & 31;
    const int warp = tid >> 5;
    const int wm = (warp >> 1) * 32;
    const int wn = (warp & 1) * 64;

    const uint32_t smb = smem_u32(sm);

    auto issue_tile = [&](int k, int b) {
        const uint32_t sb = smb + (uint32_t)(b * QKV_STAGE) * 4u;
#pragma unroll
        for (int i = 0; i < 4; i++) {
            int f4  = tid + i * 256;
            int row = f4 >> 3;
            int c4  = (f4 & 7) * 4;
            cp_async16(sb + (uint32_t)(QKV_AS_OFF + row * 36 + c4) * 4u,
                       X + (size_t)(m0blk + row) * D_IN + k * 32 + c4);
        }
#pragma unroll
        for (int i = 0; i < 4; i++) {
            int f4  = tid + i * 256;
            int row = f4 >> 5;
            int c4  = (f4 & 31) * 4;
            cp_async16(sb + (uint32_t)(QKV_BS_OFF + row * 136 + c4) * 4u,
                       W + (size_t)(k * 32 + row) * D_OUT + n0blk + c4);
        }
        cp_commit();
    };

    float c[2][8][4];
#pragma unroll
    for (int mi = 0; mi < 2; mi++)
#pragma unroll
        for (int nb = 0; nb < 8; nb++)
#pragma unroll
            for (int j = 0; j < 4; j++) c[mi][nb][j] = 0.f;

    issue_tile(0, 0);

    const int NK = D_IN / 32;
    for (int k = 0; k < NK; k++) {
        const int b = k & 1;
        if (k + 1 < NK) { issue_tile(k + 1, (k + 1) & 1); cp_wait<1>(); }
        else            { cp_wait<0>(); }
        __syncthreads();

        const float* As = sm + b * QKV_STAGE + QKV_AS_OFF;
        const float* Bs = sm + b * QKV_STAGE + QKV_BS_OFF;

#pragma unroll
        for (int ks = 0; ks < 4; ks++) {
            uint32_t a[2][4];
#pragma unroll
            for (int mi = 0; mi < 2; mi++) {
                int r  = wm + mi * 16 + (lane >> 2);
                int cc = ks * 8 + (lane & 3);
                a[mi][0] = __float_as_uint(As[r * 36 + cc]);
                a[mi][1] = __float_as_uint(As[(r + 8) * 36 + cc]);
                a[mi][2] = __float_as_uint(As[r * 36 + cc + 4]);
                a[mi][3] = __float_as_uint(As[(r + 8) * 36 + cc + 4]);
            }
#pragma unroll
            for (int nb = 0; nb < 8; nb++) {
                int col = wn + nb * 8 + (lane >> 2);
                int kr  = ks * 8 + (lane & 3);
                uint32_t b0 = __float_as_uint(Bs[kr * 136 + col]);
                uint32_t b1 = __float_as_uint(Bs[(kr + 4) * 136 + col]);
                mma_tf32(c[0][nb][0], c[0][nb][1], c[0][nb][2], c[0][nb][3],
                         a[0][0], a[0][1], a[0][2], a[0][3], b0, b1);
                mma_tf32(c[1][nb][0], c[1][nb][1], c[1][nb][2], c[1][nb][3],
                         a[1][0], a[1][1], a[1][2], a[1][3], b0, b1);
            }
        }
        __syncthreads();
    }

    // epilogue: bias, tf32-round, scatter to permuted layouts
    const bool isV = (blockIdx.z == 2);
#pragma unroll
    for (int mi = 0; mi < 2; mi++) {
#pragma unroll
        for (int nb = 0; nb < 8; nb++) {
            int row = m0blk + wm + mi * 16 + (lane >> 2);
            int col = n0blk + wn + nb * 8 + 2 * (lane & 3);
            int b_ = row >> 11;
            int t_ = row & 2047;
            int h  = col >> 6;
            int d  = col & 63;
            float v00 = to_tf32(c[mi][nb][0] + bias[col]);
            float v01 = to_tf32(c[mi][nb][1] + bias[col + 1]);
            float v10 = to_tf32(c[mi][nb][2] + bias[col]);
            float v11 = to_tf32(c[mi][nb][3] + bias[col + 1]);
            if (isV) {
                // V_T[bh][d][t'] with t' pair-permuted within 8-groups
                size_t base = (((size_t)(b_ * NH + h)) * HD + d) * TT;
                int t0p = (t_ & ~7) | perm8(t_ & 7);
                int t1p = ((t_ + 8) & ~7) | perm8(t_ & 7);
                dst[base + t0p]      = v00;   // V[t,   d]
                dst[base + TT + t0p] = v01;   // V[t,   d+1]
                dst[base + t1p]      = v10;   // V[t+8, d]
                dst[base + TT + t1p] = v11;   // V[t+8, d+1]
            } else {
                // Q/K: [bh][t][d'] with d' pair-permuted within 8-groups
                size_t base = (((size_t)(b_ * NH + h)) * TT) * HD;
                int d0p = (d & ~7) | perm8(d & 7);
                int d1p = (d & ~7) | perm8((d + 1) & 7);
                dst[base + (size_t)t_ * HD + d0p]       = v00;
                dst[base + (size_t)t_ * HD + d1p]       = v01;
                dst[base + (size_t)(t_ + 8) * HD + d0p] = v10;
                dst[base + (size_t)(t_ + 8) * HD + d1p] = v11;
            }
        }
    }
}

// ---------------------------------------------------------------------------
// Kernel B: causal flash attention, 128 q-rows/CTA (4 warps x 32 rows),
// KV tiles of 64, cp.async double-buffered, LDS.64 fragment loads via
// permuted layouts. Stride 72 floats -> conflict-free LDS.64.
// smem: K0|K1|VT0|VT1 (64x72 each) | P (128x72)
// ---------------------------------------------------------------------------
#define KV_TILE   (64*72)
#define P_OFF     (4*KV_TILE)
#define ATT_SMEMF (4*KV_TILE + 128*72)   // 27648 floats = 110592 B

__global__ __launch_bounds__(128) void attn_kernel(float* __restrict__ out)
{
    extern __shared__ float sm[];
    const int tid  = threadIdx.x;
    const int lane = tid & 31;
    const int warp = tid >> 5;
    const int lam  = lane & 3;          // λ
    const int lrow = lane >> 2;

    const int bid = blockIdx.x;
    const int qt  = (TT/128 - 1) - (bid >> 6);   // longest first
    const int bh  = bid & 63;

    const float* Qb = g_Q + (size_t)bh * TT * HD;
    const float* Kb = g_K + (size_t)bh * TT * HD;
    const float* Vb = g_V + (size_t)bh * HD * TT;   // [d][t'] layout

    const int q0 = qt * 128;
    const int ktmax = 2 * qt + 1;
    const uint32_t smb = smem_u32(sm);
    float* sP = sm + P_OFF;

    auto issue_kv = [&](int kt, int b) {
        const uint32_t kdst = smb + (uint32_t)(b * KV_TILE) * 4u;
        const uint32_t vdst = smb + (uint32_t)((2 + b) * KV_TILE) * 4u;
#pragma unroll
        for (int i = 0; i < 8; i++) {
            int f4  = tid + i * 128;
            int row = f4 >> 4;               // K: t-row   V_T: d-row
            int c4  = (f4 & 15) * 4;
            uint32_t so = (uint32_t)(row * 72 + c4) * 4u;
            cp_async16(kdst + so, Kb + (size_t)(kt * 64 + row) * HD + c4);
            cp_async16(vdst + so, Vb + (size_t)row * TT + kt * 64 + c4);
        }
        cp_commit();
    };

    // prologue: start tile 0; stage Q (128x64, already permuted) into sP
    issue_kv(0, 0);
#pragma unroll
    for (int i = 0; i < 16; i++) {
        int f4  = tid + i * 128;
        int row = f4 >> 4;
        int c4  = (f4 & 15) * 4;
        float4 v = *(const float4*)(Qb + (size_t)(q0 + row) * HD + c4);
        *(float4*)(sP + row * 72 + c4) = v;
    }
    __syncthreads();

    uint32_t qa[2][8][4];
#pragma unroll
    for (int mi = 0; mi < 2; mi++) {
        int r = warp * 32 + mi * 16 + lrow;
#pragma unroll
        for (int ks = 0; ks < 8; ks++) {
            int cc = ks * 8 + 2 * lam;
            uint2 q02 = *(const uint2*)(sP + r * 72 + cc);
            uint2 q13 = *(const uint2*)(sP + (r + 8) * 72 + cc);
            qa[mi][ks][0] = q02.x; qa[mi][ks][2] = q02.y;
            qa[mi][ks][1] = q13.x; qa[mi][ks][3] = q13.y;
        }
    }

    float o[2][8][4];
#pragma unroll
    for (int mi = 0; mi < 2; mi++)
#pragma unroll
        for (int nb = 0; nb < 8; nb++)
#pragma unroll
            for (int j = 0; j < 4; j++) o[mi][nb][j] = 0.f;
    float m_[2][2] = {{-1e30f, -1e30f}, {-1e30f, -1e30f}};
    float l_[2][2] = {{0.f, 0.f}, {0.f, 0.f}};

    const int wrow = q0 + warp * 32 + lrow;

    for (int kt = 0; kt <= ktmax; kt++) {
        const int b = kt & 1;
        __syncthreads();
        if (kt + 1 <= ktmax) { issue_kv(kt + 1, (kt + 1) & 1); cp_wait<1>(); }
        else                 { cp_wait<0>(); }
        __syncthreads();

        if (kt * 64 > q0 + warp * 32 + 31) continue;   // fully masked warp

        float* sK = sm + b * KV_TILE;
        float* sV = sm + (2 + b) * KV_TILE;            // V_T tile [d][t-chunk]

        // S = Q * K^T
        float s[2][8][4];
#pragma unroll
        for (int mi = 0; mi < 2; mi++)
#pragma unroll
            for (int nb = 0; nb < 8; nb++)
#pragma unroll
                for (int j = 0; j < 4; j++) s[mi][nb][j] = 0.f;

#pragma unroll
        for (int ks = 0; ks < 8; ks++) {
#pragma unroll
            for (int nb = 0; nb < 8; nb++) {
                int n = nb * 8 + lrow;
                uint2 bb = *(const uint2*)(sK + n * 72 + ks * 8 + 2 * lam);
                mma_tf32(s[0][nb][0], s[0][nb][1], s[0][nb][2], s[0][nb][3],
                         qa[0][ks][0], qa[0][ks][1], qa[0][ks][2], qa[0][ks][3],
                         bb.x, bb.y);
                mma_tf32(s[1][nb][0], s[1][nb][1], s[1][nb][2], s[1][nb][3],
                         qa[1][ks][0], qa[1][ks][1], qa[1][ks][2], qa[1][ks][3],
                         bb.x, bb.y);
            }
        }

        // scale, causal mask, online softmax
        const bool diag = (kt >= 2 * qt);
#pragma unroll
        for (int mi = 0; mi < 2; mi++) {
            const int r0 = wrow + mi * 16;
            const int r1 = r0 + 8;
            float tm0 = -1e30f, tm1 = -1e30f;
#pragma unroll
            for (int nb = 0; nb < 8; nb++) {
                int kv = kt * 64 + nb * 8 + 2 * lam;
                s[mi][nb][0] *= 0.125f; if (diag && kv     > r0) s[mi][nb][0] = -1e30f;
                s[mi][nb][1] *= 0.125f; if (diag && kv + 1 > r0) s[mi][nb][1] = -1e30f;
                s[mi][nb][2] *= 0.125f; if (diag && kv     > r1) s[mi][nb][2] = -1e30f;
                s[mi][nb][3] *= 0.125f; if (diag && kv + 1 > r1) s[mi][nb][3] = -1e30f;
                tm0 = fmaxf(tm0, fmaxf(s[mi][nb][0], s[mi][nb][1]));
                tm1 = fmaxf(tm1, fmaxf(s[mi][nb][2], s[mi][nb][3]));
            }
            tm0 = fmaxf(tm0, __shfl_xor_sync(0xffffffffu, tm0, 1));
            tm0 = fmaxf(tm0, __shfl_xor_sync(0xffffffffu, tm0, 2));
            tm1 = fmaxf(tm1, __shfl_xor_sync(0xffffffffu, tm1, 1));
            tm1 = fmaxf(tm1, __shfl_xor_sync(0xffffffffu, tm1, 2));

            float mn0 = fmaxf(m_[mi][0], tm0), mn1 = fmaxf(m_[mi][1], tm1);
            float al0 = __expf(m_[mi][0] - mn0), al1 = __expf(m_[mi][1] - mn1);
            float rs0 = 0.f, rs1 = 0.f;
#pragma unroll
            for (int nb = 0; nb < 8; nb++) {
                s[mi][nb][0] = __expf(s[mi][nb][0] - mn0); rs0 += s[mi][nb][0];
                s[mi][nb][1] = __expf(s[mi][nb][1] - mn0); rs0 += s[mi][nb][1];
                s[mi][nb][2] = __expf(s[mi][nb][2] - mn1); rs1 += s[mi][nb][2];
                s[mi][nb][3] = __expf(s[mi][nb][3] - mn1); rs1 += s[mi][nb][3];
                o[mi][nb][0] *= al0; o[mi][nb][1] *= al0;
                o[mi][nb][2] *= al1; o[mi][nb][3] *= al1;
            }
            rs0 += __shfl_xor_sync(0xffffffffu, rs0, 1);
            rs0 += __shfl_xor_sync(0xffffffffu, rs0, 2);
            rs1 += __shfl_xor_sync(0xffffffffu, rs1, 1);
            rs1 += __shfl_xor_sync(0xffffffffu, rs1, 2);
            l_[mi][0] = l_[mi][0] * al0 + rs0;
            l_[mi][1] = l_[mi][1] * al1 + rs1;
            m_[mi][0] = mn0; m_[mi][1] = mn1;
        }

        // store P (warp-private rows) at pair-permuted columns
#pragma unroll
        for (int mi = 0; mi < 2; mi++) {
            int r = warp * 32 + mi * 16 + lrow;
#pragma unroll
            for (int nb = 0; nb < 8; nb++) {
                int pc0 = nb * 8 + perm8(2 * lam);
                int pc1 = nb * 8 + perm8(2 * lam + 1);
                sP[r * 72 + pc0]       = to_tf32(s[mi][nb][0]);
                sP[r * 72 + pc1]       = to_tf32(s[mi][nb][1]);
                sP[(r + 8) * 72 + pc0] = to_tf32(s[mi][nb][2]);
                sP[(r + 8) * 72 + pc1] = to_tf32(s[mi][nb][3]);
            }
        }
        __syncwarp();

        // O += P * V  (vb from V_T tile: row=d, cols=t pair-permuted)
#pragma unroll
        for (int kc = 0; kc < 8; kc++) {
            uint32_t pa[2][4];
#pragma unroll
            for (int mi = 0; mi < 2; mi++) {
                int r  = warp * 32 + mi * 16 + lrow;
                int cc = kc * 8 + 2 * lam;
                uint2 p02 = *(const uint2*)(sP + r * 72 + cc);
                uint2 p13 = *(const uint2*)(sP + (r + 8) * 72 + cc);
                pa[mi][0] = p02.x; pa[mi][2] = p02.y;
                pa[mi][1] = p13.x; pa[mi][3] = p13.y;
            }
#pragma unroll
            for (int nb = 0; nb < 8; nb++) {
                int d = nb * 8 + lrow;
                uint2 vv = *(const uint2*)(sV + d * 72 + kc * 8 + 2 * lam);
                mma_tf32(o[0][nb][0], o[0][nb][1], o[0][nb][2], o[0][nb][3],
                         pa[0][0], pa[0][1], pa[0][2], pa[0][3], vv.x, vv.y);
                mma_tf32(o[1][nb][0], o[1][nb][1], o[1][nb][2], o[1][nb][3],
                         pa[1][0], pa[1][1], pa[1][2], pa[1][3], vv.x, vv.y);
            }
        }
        __syncwarp();
    }

    // normalize and write out[b, t, h*64 + d]
    const int b_ = bh >> 4;
    const int h  = bh & 15;
#pragma unroll
    for (int mi = 0; mi < 2; mi++) {
        float inv0 = 1.f / l_[mi][0];
        float inv1 = 1.f / l_[mi][1];
        int r0 = wrow + mi * 16;
        float* orow0 = out + ((size_t)b_ * TT + r0) * D_OUT + h * HD;
        float* orow1 = out + ((size_t)b_ * TT + r0 + 8) * D_OUT + h * HD;
#pragma unroll
        for (int nb = 0; nb < 8; nb++) {
            int cc = nb * 8 + 2 * lam;
            *(float2*)(orow0 + cc) = make_float2(o[mi][nb][0] * inv0, o[mi][nb][1] * inv0);
            *(float2*)(orow1 + cc) = make_float2(o[mi][nb][2] * inv1, o[mi][nb][3] * inv1);
        }
    }
}

// ---------------------------------------------------------------------------
extern "C" void kernel_launch(void* const* d_in, const int* in_sizes, int n_in,
                              void* d_out, int out_size)
{
    const float* X  = (const float*)d_in[0];
    const float* Wq = (const float*)d_in[1];
    const float* bq = (const float*)d_in[2];
    const float* Wk = (const float*)d_in[3];
    const float* bk = (const float*)d_in[4];
    const float* Wv = (const float*)d_in[5];
    const float* bv = (const float*)d_in[6];
    float* out = (float*)d_out;

    cudaFuncSetAttribute(qkv_kernel, cudaFuncAttributeMaxDynamicSharedMemorySize,
                         2 * QKV_STAGE * (int)sizeof(float));
    cudaFuncSetAttribute(attn_kernel, cudaFuncAttributeMaxDynamicSharedMemorySize,
                         ATT_SMEMF * (int)sizeof(float));

    float* dX; cudaGetSymbolAddress((void**)&dX, g_X);
    float* dW; cudaGetSymbolAddress((void**)&dW, g_W);

    prep_kernel<<<1024, 256>>>(X,  dX,                 NROWS*D_IN/4);
    prep_kernel<<<1024, 256>>>(Wq, dW + 0*D_IN*D_OUT,  D_IN*D_OUT/4);
    prep_kernel<<<1024, 256>>>(Wk, dW + 1*D_IN*D_OUT,  D_IN*D_OUT/4);
    prep_kernel<<<1024, 256>>>(Wv, dW + 2*D_IN*D_OUT,  D_IN*D_OUT/4);

    dim3 gA(NROWS / 128, D_OUT / 128, 3);
    qkv_kernel<<<gA, 256, 2 * QKV_STAGE * sizeof(float)>>>(bq, bk, bv);

    attn_kernel<<<(TT/128) * BB * NH, 128, ATT_SMEMF * sizeof(float)>>>(out);
}

// round 9
// speedup vs baseline: 1.2830x; 1.0581x over previous
#include <cuda_runtime.h>
#include <cstdint>

#define D_IN   1024
#define D_OUT  1024
#define NH     16
#define HD     64
#define BB     4
#define TT     2048
#define NROWS  (BB*TT)   // 8192

// ---------------------------------------------------------------------------
// Scratch (static __device__ per allocation-guard rules)
// Q, K: [bh][t][d']  (d' = head-dim with 8-group pair permutation)
// V   : [bh][d][t']  (transposed, t' permuted within 8-groups)
// ---------------------------------------------------------------------------
__device__ float g_Q[BB*NH*TT*HD];
__device__ float g_K[BB*NH*TT*HD];
__device__ float g_V[BB*NH*TT*HD];
__device__ float g_X[NROWS*D_IN];
__device__ float g_W[3][D_IN*D_OUT];

// pair permutation within an 8-group: logical (z, z+4) -> physical (2z, 2z+1)
__device__ __forceinline__ int perm8(int z) { return ((z & 3) << 1) | (z >> 2); }

__device__ __forceinline__ float to_tf32(float x) {
    uint32_t u;
    asm("cvt.rna.tf32.f32 %0, %1;" : "=r"(u) : "f"(x));
    return __uint_as_float(u);
}

__device__ __forceinline__ void mma_tf32(float& c0, float& c1, float& c2, float& c3,
                                         uint32_t a0, uint32_t a1, uint32_t a2, uint32_t a3,
                                         uint32_t b0, uint32_t b1) {
    asm volatile(
        "mma.sync.aligned.m16n8k8.row.col.f32.tf32.tf32.f32 "
        "{%0,%1,%2,%3}, {%4,%5,%6,%7}, {%8,%9}, {%0,%1,%2,%3};\n"
        : "+f"(c0), "+f"(c1), "+f"(c2), "+f"(c3)
        : "r"(a0), "r"(a1), "r"(a2), "r"(a3), "r"(b0), "r"(b1));
}

__device__ __forceinline__ uint32_t smem_u32(const void* p) {
    return (uint32_t)__cvta_generic_to_shared(p);
}
__device__ __forceinline__ void cp_async16(uint32_t dst, const void* src) {
    asm volatile("cp.async.cg.shared.global [%0], [%1], 16;" :: "r"(dst), "l"(src));
}
__device__ __forceinline__ void cp_commit() {
    asm volatile("cp.async.commit_group;");
}
template <int N>
__device__ __forceinline__ void cp_wait() {
    asm volatile("cp.async.wait_group %0;" :: "n"(N));
}

// ---------------------------------------------------------------------------
// Kernel 0: tf32-round ALL inputs (X, Wq, Wk, Wv) in one launch
// ---------------------------------------------------------------------------
#define NX4 (NROWS*D_IN/4)      // 2097152
#define NW4 (D_IN*D_OUT/4)      // 262144 = 2^18

__global__ void prep_kernel(const float* __restrict__ X,
                            const float* __restrict__ Wq,
                            const float* __restrict__ Wk,
                            const float* __restrict__ Wv)
{
    const int total = NX4 + 3 * NW4;
    int i = blockIdx.x * blockDim.x + threadIdx.x;
    int stride = gridDim.x * blockDim.x;
    for (; i < total; i += stride) {
        const float4* src;
        float4* dst;
        if (i < NX4) {
            src = (const float4*)X + i;
            dst = (float4*)g_X + i;
        } else {
            int j = i - NX4;
            int w = j >> 18;            // / NW4
            int o = j & (NW4 - 1);
            const float* sp = (w == 0) ? Wq : ((w == 1) ? Wk : Wv);
            src = (const float4*)sp + o;
            dst = (float4*)&g_W[0][0] + j;
        }
        float4 v = *src;
        v.x = to_tf32(v.x); v.y = to_tf32(v.y); v.z = to_tf32(v.z); v.w = to_tf32(v.w);
        *dst = v;
    }
}

// ---------------------------------------------------------------------------
// Kernel A: QKV projection (cp.async double buffer), permuted epilogue.
// ---------------------------------------------------------------------------
#define QKV_STAGE   (128*36 + 32*136)
#define QKV_AS_OFF  0
#define QKV_BS_OFF  (128*36)

__global__ __launch_bounds__(256) void qkv_kernel(
    const float* __restrict__ bq,
    const float* __restrict__ bk,
    const float* __restrict__ bv)
{
    extern __shared__ float sm[];

    const float* X = g_X;
    const float* W = g_W[blockIdx.z];
    const float* bias;
    float* dst;
    if (blockIdx.z == 0)      { bias = bq; dst = g_Q; }
    else if (blockIdx.z == 1) { bias = bk; dst = g_K; }
    else                      { bias = bv; dst = g_V; }

    const int m0blk = blockIdx.x * 128;
    const int n0blk = blockIdx.y * 128;
    const int tid  = threadIdx.x;
    const int lane = tid & 31;
    const int warp = tid >> 5;
    const int wm = (warp >> 1) * 32;
    const int wn = (warp & 1) * 64;

    const uint32_t smb = smem_u32(sm);

    auto issue_tile = [&](int k, int b) {
        const uint32_t sb = smb + (uint32_t)(b * QKV_STAGE) * 4u;
#pragma unroll
        for (int i = 0; i < 4; i++) {
            int f4  = tid + i * 256;
            int row = f4 >> 3;
            int c4  = (f4 & 7) * 4;
            cp_async16(sb + (uint32_t)(QKV_AS_OFF + row * 36 + c4) * 4u,
                       X + (size_t)(m0blk + row) * D_IN + k * 32 + c4);
        }
#pragma unroll
        for (int i = 0; i < 4; i++) {
            int f4  = tid + i * 256;
            int row = f4 >> 5;
            int c4  = (f4 & 31) * 4;
            cp_async16(sb + (uint32_t)(QKV_BS_OFF + row * 136 + c4) * 4u,
                       W + (size_t)(k * 32 + row) * D_OUT + n0blk + c4);
        }
        cp_commit();
    };

    float c[2][8][4];
#pragma unroll
    for (int mi = 0; mi < 2; mi++)
#pragma unroll
        for (int nb = 0; nb < 8; nb++)
#pragma unroll
            for (int j = 0; j < 4; j++) c[mi][nb][j] = 0.f;

    issue_tile(0, 0);

    const int NK = D_IN / 32;
    for (int k = 0; k < NK; k++) {
        const int b = k & 1;
        if (k + 1 < NK) { issue_tile(k + 1, (k + 1) & 1); cp_wait<1>(); }
        else            { cp_wait<0>(); }
        __syncthreads();

        const float* As = sm + b * QKV_STAGE + QKV_AS_OFF;
        const float* Bs = sm + b * QKV_STAGE + QKV_BS_OFF;

#pragma unroll
        for (int ks = 0; ks < 4; ks++) {
            uint32_t a[2][4];
#pragma unroll
            for (int mi = 0; mi < 2; mi++) {
                int r  = wm + mi * 16 + (lane >> 2);
                int cc = ks * 8 + (lane & 3);
                a[mi][0] = __float_as_uint(As[r * 36 + cc]);
                a[mi][1] = __float_as_uint(As[(r + 8) * 36 + cc]);
                a[mi][2] = __float_as_uint(As[r * 36 + cc + 4]);
                a[mi][3] = __float_as_uint(As[(r + 8) * 36 + cc + 4]);
            }
#pragma unroll
            for (int nb = 0; nb < 8; nb++) {
                int col = wn + nb * 8 + (lane >> 2);
                int kr  = ks * 8 + (lane & 3);
                uint32_t b0 = __float_as_uint(Bs[kr * 136 + col]);
                uint32_t b1 = __float_as_uint(Bs[(kr + 4) * 136 + col]);
                mma_tf32(c[0][nb][0], c[0][nb][1], c[0][nb][2], c[0][nb][3],
                         a[0][0], a[0][1], a[0][2], a[0][3], b0, b1);
                mma_tf32(c[1][nb][0], c[1][nb][1], c[1][nb][2], c[1][nb][3],
                         a[1][0], a[1][1], a[1][2], a[1][3], b0, b1);
            }
        }
        __syncthreads();
    }

    const bool isV = (blockIdx.z == 2);
#pragma unroll
    for (int mi = 0; mi < 2; mi++) {
#pragma unroll
        for (int nb = 0; nb < 8; nb++) {
            int row = m0blk + wm + mi * 16 + (lane >> 2);
            int col = n0blk + wn + nb * 8 + 2 * (lane & 3);
            int b_ = row >> 11;
            int t_ = row & 2047;
            int h  = col >> 6;
            int d  = col & 63;
            float v00 = to_tf32(c[mi][nb][0] + bias[col]);
            float v01 = to_tf32(c[mi][nb][1] + bias[col + 1]);
            float v10 = to_tf32(c[mi][nb][2] + bias[col]);
            float v11 = to_tf32(c[mi][nb][3] + bias[col + 1]);
            if (isV) {
                size_t base = (((size_t)(b_ * NH + h)) * HD + d) * TT;
                int t0p = (t_ & ~7) | perm8(t_ & 7);
                int t1p = ((t_ + 8) & ~7) | perm8(t_ & 7);
                dst[base + t0p]      = v00;
                dst[base + TT + t0p] = v01;
                dst[base + t1p]      = v10;
                dst[base + TT + t1p] = v11;
            } else {
                size_t base = (((size_t)(b_ * NH + h)) * TT) * HD;
                int d0p = (d & ~7) | perm8(d & 7);
                int d1p = (d & ~7) | perm8((d + 1) & 7);
                dst[base + (size_t)t_ * HD + d0p]       = v00;
                dst[base + (size_t)t_ * HD + d1p]       = v01;
                dst[base + (size_t)(t_ + 8) * HD + d0p] = v10;
                dst[base + (size_t)(t_ + 8) * HD + d1p] = v11;
            }
        }
    }
}

// ---------------------------------------------------------------------------
// Kernel B: causal flash attention.
// 256 threads = 8 warps x 16 q-rows = 128 q-rows/CTA. KV tiles of 64,
// cp.async double-buffered. Q persistent in smem (frags reloaded per tile);
// P relayout accumulator->A-operand via register shuffles (no smem P).
// smem: K0|K1|VT0|VT1 (64x72) + Q (128x72) = 110.6KB -> 2 CTAs/SM, 16 warps.
// ---------------------------------------------------------------------------
#define KV_TILE   (64*72)
#define Q_OFF     (4*KV_TILE)
#define ATT_SMEMF (4*KV_TILE + 128*72)

__global__ __launch_bounds__(256, 2) void attn_kernel(float* __restrict__ out)
{
    extern __shared__ float sm[];
    const int tid  = threadIdx.x;
    const int lane = tid & 31;
    const int warp = tid >> 5;          // 0..7
    const int lam  = lane & 3;
    const int lrow = lane >> 2;

    const int bid = blockIdx.x;
    const int qt  = (TT/128 - 1) - (bid >> 6);   // longest first
    const int bh  = bid & 63;

    const float* Qb = g_Q + (size_t)bh * TT * HD;
    const float* Kb = g_K + (size_t)bh * TT * HD;
    const float* Vb = g_V + (size_t)bh * HD * TT;   // [d][t'] layout

    const int q0 = qt * 128;
    const int ktmax = 2 * qt + 1;
    const uint32_t smb = smem_u32(sm);
    float* sQ = sm + Q_OFF;

    auto issue_kv = [&](int kt, int b) {
        const uint32_t kdst = smb + (uint32_t)(b * KV_TILE) * 4u;
        const uint32_t vdst = smb + (uint32_t)((2 + b) * KV_TILE) * 4u;
#pragma unroll
        for (int i = 0; i < 4; i++) {
            int f4  = tid + i * 256;
            int row = f4 >> 4;
            int c4  = (f4 & 15) * 4;
            uint32_t so = (uint32_t)(row * 72 + c4) * 4u;
            cp_async16(kdst + so, Kb + (size_t)(kt * 64 + row) * HD + c4);
            cp_async16(vdst + so, Vb + (size_t)row * TT + kt * 64 + c4);
        }
        cp_commit();
    };

    // prologue: start tile 0; stage Q (128x64, permuted layout) into sQ
    issue_kv(0, 0);
#pragma unroll
    for (int i = 0; i < 8; i++) {
        int f4  = tid + i * 256;
        int row = f4 >> 4;
        int c4  = (f4 & 15) * 4;
        float4 v = *(const float4*)(Qb + (size_t)(q0 + row) * HD + c4);
        *(float4*)(sQ + row * 72 + c4) = v;
    }
    __syncthreads();

    float o[8][4];
#pragma unroll
    for (int nb = 0; nb < 8; nb++)
#pragma unroll
        for (int j = 0; j < 4; j++) o[nb][j] = 0.f;
    float m0 = -1e30f, m1 = -1e30f, l0 = 0.f, l1 = 0.f;

    const int wrow = q0 + warp * 16 + lrow;
    const int qsrc = lane & ~3;          // base lane of this row quad

    for (int kt = 0; kt <= ktmax; kt++) {
        const int b = kt & 1;
        __syncthreads();
        if (kt + 1 <= ktmax) { issue_kv(kt + 1, (kt + 1) & 1); cp_wait<1>(); }
        else                 { cp_wait<0>(); }
        __syncthreads();

        if (kt * 64 > q0 + warp * 16 + 15) continue;   // fully masked warp

        float* sK = sm + b * KV_TILE;
        float* sV = sm + (2 + b) * KV_TILE;

        // Q fragments for this tile (from persistent sQ)
        uint32_t qa[8][4];
        {
            int r = warp * 16 + lrow;
#pragma unroll
            for (int ks = 0; ks < 8; ks++) {
                uint2 q02 = *(const uint2*)(sQ + r * 72 + ks * 8 + 2 * lam);
                uint2 q13 = *(const uint2*)(sQ + (r + 8) * 72 + ks * 8 + 2 * lam);
                qa[ks][0] = q02.x; qa[ks][2] = q02.y;
                qa[ks][1] = q13.x; qa[ks][3] = q13.y;
            }
        }

        // S = Q * K^T (16 rows x 64 kv per warp)
        float s[8][4];
#pragma unroll
        for (int nb = 0; nb < 8; nb++)
#pragma unroll
            for (int j = 0; j < 4; j++) s[nb][j] = 0.f;

#pragma unroll
        for (int ks = 0; ks < 8; ks++) {
#pragma unroll
            for (int nb = 0; nb < 8; nb++) {
                int n = nb * 8 + lrow;
                uint2 bb = *(const uint2*)(sK + n * 72 + ks * 8 + 2 * lam);
                mma_tf32(s[nb][0], s[nb][1], s[nb][2], s[nb][3],
                         qa[ks][0], qa[ks][1], qa[ks][2], qa[ks][3], bb.x, bb.y);
            }
        }

        // scale, causal mask, online softmax (rows wrow, wrow+8)
        const bool diag = (kt >= 2 * qt);
        const int r0 = wrow, r1 = wrow + 8;
        float tm0 = -1e30f, tm1 = -1e30f;
#pragma unroll
        for (int nb = 0; nb < 8; nb++) {
            int kv = kt * 64 + nb * 8 + 2 * lam;
            s[nb][0] *= 0.125f; if (diag && kv     > r0) s[nb][0] = -1e30f;
            s[nb][1] *= 0.125f; if (diag && kv + 1 > r0) s[nb][1] = -1e30f;
            s[nb][2] *= 0.125f; if (diag && kv     > r1) s[nb][2] = -1e30f;
            s[nb][3] *= 0.125f; if (diag && kv + 1 > r1) s[nb][3] = -1e30f;
            tm0 = fmaxf(tm0, fmaxf(s[nb][0], s[nb][1]));
            tm1 = fmaxf(tm1, fmaxf(s[nb][2], s[nb][3]));
        }
        tm0 = fmaxf(tm0, __shfl_xor_sync(0xffffffffu, tm0, 1));
        tm0 = fmaxf(tm0, __shfl_xor_sync(0xffffffffu, tm0, 2));
        tm1 = fmaxf(tm1, __shfl_xor_sync(0xffffffffu, tm1, 1));
        tm1 = fmaxf(tm1, __shfl_xor_sync(0xffffffffu, tm1, 2));

        float mn0 = fmaxf(m0, tm0), mn1 = fmaxf(m1, tm1);
        float al0 = __expf(m0 - mn0), al1 = __expf(m1 - mn1);
        float rs0 = 0.f, rs1 = 0.f;
#pragma unroll
        for (int nb = 0; nb < 8; nb++) {
            s[nb][0] = __expf(s[nb][0] - mn0); rs0 += s[nb][0];
            s[nb][1] = __expf(s[nb][1] - mn0); rs0 += s[nb][1];
            s[nb][2] = __expf(s[nb][2] - mn1); rs1 += s[nb][2];
            s[nb][3] = __expf(s[nb][3] - mn1); rs1 += s[nb][3];
            o[nb][0] *= al0; o[nb][1] *= al0;
            o[nb][2] *= al1; o[nb][3] *= al1;
        }
        rs0 += __shfl_xor_sync(0xffffffffu, rs0, 1);
        rs0 += __shfl_xor_sync(0xffffffffu, rs0, 2);
        rs1 += __shfl_xor_sync(0xffffffffu, rs1, 1);
        rs1 += __shfl_xor_sync(0xffffffffu, rs1, 2);
        l0 = l0 * al0 + rs0;
        l1 = l1 * al1 + rs1;
        m0 = mn0; m1 = mn1;

        // O += P * V. P A-operand built from S accumulator via shuffles:
        // accumulator: lane(r,λ) holds P[r, nb*8+2λ(+1)], P[r+8, ...]
        // A-operand chunk kc: lane needs P[r, kc*8+λ], P[r+8, +λ], +λ+4.
#pragma unroll
        for (int kc = 0; kc < 8; kc++) {
            int src0 = qsrc | (lam >> 1);
            int src2 = qsrc | 2 | (lam >> 1);
            float v00 = __shfl_sync(0xffffffffu, s[kc][0], src0);
            float v01 = __shfl_sync(0xffffffffu, s[kc][1], src0);
            float v20 = __shfl_sync(0xffffffffu, s[kc][0], src2);
            float v21 = __shfl_sync(0xffffffffu, s[kc][1], src2);
            float w00 = __shfl_sync(0xffffffffu, s[kc][2], src0);
            float w01 = __shfl_sync(0xffffffffu, s[kc][3], src0);
            float w20 = __shfl_sync(0xffffffffu, s[kc][2], src2);
            float w21 = __shfl_sync(0xffffffffu, s[kc][3], src2);
            bool oddl = (lam & 1);
            uint32_t a0 = __float_as_uint(to_tf32(oddl ? v01 : v00));
            uint32_t a1 = __float_as_uint(to_tf32(oddl ? w01 : w00));
            uint32_t a2 = __float_as_uint(to_tf32(oddl ? v21 : v20));
            uint32_t a3 = __float_as_uint(to_tf32(oddl ? w21 : w20));
#pragma unroll
            for (int nb = 0; nb < 8; nb++) {
                int d = nb * 8 + lrow;
                uint2 vv = *(const uint2*)(sV + d * 72 + kc * 8 + 2 * lam);
                mma_tf32(o[nb][0], o[nb][1], o[nb][2], o[nb][3],
                         a0, a1, a2, a3, vv.x, vv.y);
            }
        }
    }

    // normalize and write out[b, t, h*64 + d]
    const int b_ = bh >> 4;
    const int h  = bh & 15;
    float inv0 = 1.f / l0;
    float inv1 = 1.f / l1;
    float* orow0 = out + ((size_t)b_ * TT + wrow) * D_OUT + h * HD;
    float* orow1 = out + ((size_t)b_ * TT + wrow + 8) * D_OUT + h * HD;
#pragma unroll
    for (int nb = 0; nb < 8; nb++) {
        int cc = nb * 8 + 2 * lam;
        *(float2*)(orow0 + cc) = make_float2(o[nb][0] * inv0, o[nb][1] * inv0);
        *(float2*)(orow1 + cc) = make_float2(o[nb][2] * inv1, o[nb][3] * inv1);
    }
}

// ---------------------------------------------------------------------------
extern "C" void kernel_launch(void* const* d_in, const int* in_sizes, int n_in,
                              void* d_out, int out_size)
{
    const float* X  = (const float*)d_in[0];
    const float* Wq = (const float*)d_in[1];
    const float* bq = (const float*)d_in[2];
    const float* Wk = (const float*)d_in[3];
    const float* bk = (const float*)d_in[4];
    const float* Wv = (const float*)d_in[5];
    const float* bv = (const float*)d_in[6];
    float* out = (float*)d_out;

    cudaFuncSetAttribute(qkv_kernel, cudaFuncAttributeMaxDynamicSharedMemorySize,
                         2 * QKV_STAGE * (int)sizeof(float));
    cudaFuncSetAttribute(attn_kernel, cudaFuncAttributeMaxDynamicSharedMemorySize,
                         ATT_SMEMF * (int)sizeof(float));

    prep_kernel<<<2048, 256>>>(X, Wq, Wk, Wv);

    dim3 gA(NROWS / 128, D_OUT / 128, 3);
    qkv_kernel<<<gA, 256, 2 * QKV_STAGE * sizeof(float)>>>(bq, bk, bv);

    attn_kernel<<<(TT/128) * BB * NH, 256, ATT_SMEMF * sizeof(float)>>>(out);
}